// round 2
// baseline (speedup 1.0000x reference)
#include <cuda_runtime.h>
#include <math.h>

#define TT 128
#define BB 512
#define DD 300
#define HH 512
#define G3 1536

// Scratch: gi = x@Wih^T + bih for all timesteps, per direction; seq = per-layer
// hidden states for all timesteps, per direction (overwritten layer by layer).
__device__ float g_gi[2][(size_t)TT * BB * G3];   // 2 x 402 MB
__device__ float g_seq[2][(size_t)TT * BB * HH];  // 2 x 134 MB

__device__ __forceinline__ float sigmoidf_(float x) { return 1.f / (1.f + expf(-x)); }

// ---------------------------------------------------------------------------
// gi GEMM: C[t*B+b, n] = sum_k A[t*B+b, k] * W[n, k] + bias[n]
// A is input_sequence (layer 0; dir 1 reads reversed time) or g_seq[dir].
// Tiles: 64x64, K-tile 16, 256 threads, 4x4 per thread.
// ---------------------------------------------------------------------------
__global__ __launch_bounds__(256) void gi_gemm(
    const float* __restrict__ x, int K, int is_layer0,
    const float* __restrict__ Wf, const float* __restrict__ Wb,
    const float* __restrict__ bf, const float* __restrict__ bb)
{
    __shared__ float As[16][66];
    __shared__ float Bs[16][66];

    const int dir = blockIdx.z;
    const float* W    = dir ? Wb : Wf;
    const float* bias = dir ? bb : bf;
    const int n0 = blockIdx.x * 64;
    const int m0 = blockIdx.y * 64;
    const int t = m0 / BB;           // 64 | 512, so t constant per tile
    const int brow0 = m0 % BB;

    const float* A;
    if (is_layer0) {
        const int tt = dir ? (TT - 1 - t) : t;
        A = x + ((size_t)tt * BB + brow0) * K;
    } else {
        A = &g_seq[dir][((size_t)t * BB + brow0) * HH];
    }
    float* C = &g_gi[dir][(size_t)m0 * G3];

    const int tid = threadIdx.x;
    const int tx = tid & 15, ty = tid >> 4;

    float acc[4][4];
    #pragma unroll
    for (int i = 0; i < 4; i++)
        #pragma unroll
        for (int j = 0; j < 4; j++) acc[i][j] = 0.f;

    for (int k0 = 0; k0 < K; k0 += 16) {
        #pragma unroll
        for (int i = 0; i < 4; i++) {
            const int e = tid + i * 256;
            const int kk = e & 15, mm = e >> 4;
            const int k = k0 + kk;
            As[kk][mm] = (k < K) ? A[(size_t)mm * K + k] : 0.f;
            Bs[kk][mm] = (k < K) ? W[(size_t)(n0 + mm) * K + k] : 0.f;
        }
        __syncthreads();
        #pragma unroll
        for (int kk = 0; kk < 16; kk++) {
            float a[4], b[4];
            #pragma unroll
            for (int i = 0; i < 4; i++) a[i] = As[kk][ty * 4 + i];
            #pragma unroll
            for (int j = 0; j < 4; j++) b[j] = Bs[kk][tx * 4 + j];
            #pragma unroll
            for (int i = 0; i < 4; i++)
                #pragma unroll
                for (int j = 0; j < 4; j++)
                    acc[i][j] += a[i] * b[j];
        }
        __syncthreads();
    }

    #pragma unroll
    for (int i = 0; i < 4; i++) {
        const int m = ty * 4 + i;
        #pragma unroll
        for (int j = 0; j < 4; j++) {
            const int n = n0 + tx * 4 + j;
            C[(size_t)m * G3 + n] = acc[i][j] + bias[n];
        }
    }
}

// ---------------------------------------------------------------------------
// Fused recurrent step: gh = h_{t-1} @ Whh^T (3 gates) + gate math.
// Reads g_seq[dir] at t-1, g_gi[dir] at t; writes g_seq[dir] at t.
// Grid: (H/64, B/64, 2). Each thread: 4x4 outputs x 3 gate accumulators.
// ---------------------------------------------------------------------------
__global__ __launch_bounds__(256) void gru_step(
    int t,
    const float* __restrict__ Whhf, const float* __restrict__ Whhb,
    const float* __restrict__ bhf,  const float* __restrict__ bhb)
{
    __shared__ float As[16][66];
    __shared__ float Bs[3][16][66];

    const int dir = blockIdx.z;
    const float* Whh = dir ? Whhb : Whhf;
    const float* bhh = dir ? bhb : bhf;
    const int n0 = blockIdx.x * 64;   // over H
    const int m0 = blockIdx.y * 64;   // over B

    const float* gi   = &g_gi[dir][((size_t)t * BB + m0) * G3];
    float* hout       = &g_seq[dir][((size_t)t * BB + m0) * HH];
    const float* hprev = (t > 0) ? &g_seq[dir][((size_t)(t - 1) * BB + m0) * HH] : nullptr;

    const int tid = threadIdx.x;
    const int tx = tid & 15, ty = tid >> 4;

    float ar[4][4], az[4][4], an[4][4];
    #pragma unroll
    for (int i = 0; i < 4; i++)
        #pragma unroll
        for (int j = 0; j < 4; j++) { ar[i][j] = 0.f; az[i][j] = 0.f; an[i][j] = 0.f; }

    if (t > 0) {
        for (int k0 = 0; k0 < HH; k0 += 16) {
            #pragma unroll
            for (int i = 0; i < 4; i++) {
                const int e = tid + i * 256;
                const int kk = e & 15, mm = e >> 4;
                As[kk][mm] = hprev[(size_t)mm * HH + k0 + kk];
            }
            #pragma unroll
            for (int g = 0; g < 3; g++) {
                #pragma unroll
                for (int i = 0; i < 4; i++) {
                    const int e = tid + i * 256;
                    const int kk = e & 15, nn = e >> 4;
                    Bs[g][kk][nn] = Whh[(size_t)(g * HH + n0 + nn) * HH + k0 + kk];
                }
            }
            __syncthreads();
            #pragma unroll
            for (int kk = 0; kk < 16; kk++) {
                float a[4];
                #pragma unroll
                for (int i = 0; i < 4; i++) a[i] = As[kk][ty * 4 + i];
                float br[4], bz[4], bn[4];
                #pragma unroll
                for (int j = 0; j < 4; j++) {
                    br[j] = Bs[0][kk][tx * 4 + j];
                    bz[j] = Bs[1][kk][tx * 4 + j];
                    bn[j] = Bs[2][kk][tx * 4 + j];
                }
                #pragma unroll
                for (int i = 0; i < 4; i++)
                    #pragma unroll
                    for (int j = 0; j < 4; j++) {
                        ar[i][j] += a[i] * br[j];
                        az[i][j] += a[i] * bz[j];
                        an[i][j] += a[i] * bn[j];
                    }
            }
            __syncthreads();
        }
    }

    #pragma unroll
    for (int i = 0; i < 4; i++) {
        const int m = ty * 4 + i;
        #pragma unroll
        for (int j = 0; j < 4; j++) {
            const int n = n0 + tx * 4 + j;
            const float gir = gi[(size_t)m * G3 + n];
            const float giz = gi[(size_t)m * G3 + HH + n];
            const float gin = gi[(size_t)m * G3 + 2 * HH + n];
            const float hp = (t > 0) ? hprev[(size_t)m * HH + n] : 0.f;
            const float r  = sigmoidf_(gir + ar[i][j] + bhh[n]);
            const float z  = sigmoidf_(giz + az[i][j] + bhh[HH + n]);
            const float nn2 = tanhf(gin + r * (an[i][j] + bhh[2 * HH + n]));
            hout[(size_t)m * HH + n] = (1.f - z) * nn2 + z * hp;
        }
    }
}

// ---------------------------------------------------------------------------
// Projection: emb[b,:] = concat(fwd_h_last[b], bwd_h_last[b]) [2H];
// out[z=0] = emb @ W_mu^T + b_mu, out[z=1] = emb @ W_lv^T + b_lv.
// ---------------------------------------------------------------------------
__global__ __launch_bounds__(256) void proj_kernel(
    const float* __restrict__ Wmu, const float* __restrict__ bmu,
    const float* __restrict__ Wlv, const float* __restrict__ blv,
    float* __restrict__ out)
{
    __shared__ float As[16][66];
    __shared__ float Bs[16][66];

    const int which = blockIdx.z;
    const float* W    = which ? Wlv : Wmu;
    const float* bias = which ? blv : bmu;
    const int n0 = blockIdx.x * 64;
    const int m0 = blockIdx.y * 64;

    const float* hf = &g_seq[0][((size_t)(TT - 1) * BB + m0) * HH];
    const float* hb = &g_seq[1][((size_t)(TT - 1) * BB + m0) * HH];

    const int tid = threadIdx.x;
    const int tx = tid & 15, ty = tid >> 4;

    float acc[4][4];
    #pragma unroll
    for (int i = 0; i < 4; i++)
        #pragma unroll
        for (int j = 0; j < 4; j++) acc[i][j] = 0.f;

    for (int k0 = 0; k0 < 2 * HH; k0 += 16) {
        #pragma unroll
        for (int i = 0; i < 4; i++) {
            const int e = tid + i * 256;
            const int kk = e & 15, mm = e >> 4;
            const int k = k0 + kk;
            As[kk][mm] = (k < HH) ? hf[(size_t)mm * HH + k]
                                  : hb[(size_t)mm * HH + (k - HH)];
            Bs[kk][mm] = W[(size_t)(n0 + mm) * (2 * HH) + k];
        }
        __syncthreads();
        #pragma unroll
        for (int kk = 0; kk < 16; kk++) {
            float a[4], b[4];
            #pragma unroll
            for (int i = 0; i < 4; i++) a[i] = As[kk][ty * 4 + i];
            #pragma unroll
            for (int j = 0; j < 4; j++) b[j] = Bs[kk][tx * 4 + j];
            #pragma unroll
            for (int i = 0; i < 4; i++)
                #pragma unroll
                for (int j = 0; j < 4; j++)
                    acc[i][j] += a[i] * b[j];
        }
        __syncthreads();
    }

    #pragma unroll
    for (int i = 0; i < 4; i++) {
        const int m = m0 + ty * 4 + i;
        #pragma unroll
        for (int j = 0; j < 4; j++) {
            const int n = n0 + tx * 4 + j;
            out[(size_t)which * BB * HH + (size_t)m * HH + n] = acc[i][j] + bias[n];
        }
    }
}

extern "C" void kernel_launch(void* const* d_in, const int* in_sizes, int n_in,
                              void* d_out, int out_size)
{
    (void)in_sizes; (void)n_in; (void)out_size;
    const float* x       = (const float*)d_in[0];
    // d_in[1] = batch_size (compile-time constant here)
    const float* fw_Wih0 = (const float*)d_in[2];
    const float* fw_Whh0 = (const float*)d_in[3];
    const float* fw_bih0 = (const float*)d_in[4];
    const float* fw_bhh0 = (const float*)d_in[5];
    const float* fw_Wih  = (const float*)d_in[6];
    const float* fw_Whh  = (const float*)d_in[7];
    const float* fw_bih  = (const float*)d_in[8];
    const float* fw_bhh  = (const float*)d_in[9];
    const float* bw_Wih0 = (const float*)d_in[10];
    const float* bw_Whh0 = (const float*)d_in[11];
    const float* bw_bih0 = (const float*)d_in[12];
    const float* bw_bhh0 = (const float*)d_in[13];
    const float* bw_Wih  = (const float*)d_in[14];
    const float* bw_Whh  = (const float*)d_in[15];
    const float* bw_bih  = (const float*)d_in[16];
    const float* bw_bhh  = (const float*)d_in[17];
    const float* W_mu    = (const float*)d_in[18];
    const float* b_mu    = (const float*)d_in[19];
    const float* W_lv    = (const float*)d_in[20];
    const float* b_lv    = (const float*)d_in[21];
    float* out = (float*)d_out;

    const dim3 ggi(G3 / 64, (TT * BB) / 64, 2);
    const dim3 gst(HH / 64, BB / 64, 2);

    // Layer 0: gi from raw input (dir 1 reads reversed time), then 128 steps.
    gi_gemm<<<ggi, 256>>>(x, DD, 1, fw_Wih0, bw_Wih0, fw_bih0, bw_bih0);
    for (int t = 0; t < TT; t++)
        gru_step<<<gst, 256>>>(t, fw_Whh0, bw_Whh0, fw_bhh0, bw_bhh0);

    // Layers 1..2: gi from previous layer's full sequence, then 128 steps.
    for (int l = 0; l < 2; l++) {
        gi_gemm<<<ggi, 256>>>(nullptr, HH, 0,
                              fw_Wih + (size_t)l * G3 * HH, bw_Wih + (size_t)l * G3 * HH,
                              fw_bih + (size_t)l * G3,      bw_bih + (size_t)l * G3);
        for (int t = 0; t < TT; t++)
            gru_step<<<gst, 256>>>(t,
                                   fw_Whh + (size_t)l * G3 * HH, bw_Whh + (size_t)l * G3 * HH,
                                   fw_bhh + (size_t)l * G3,      bw_bhh + (size_t)l * G3);
    }

    proj_kernel<<<dim3(HH / 64, BB / 64, 2), 256>>>(W_mu, b_mu, W_lv, b_lv, out);
}

// round 4
// speedup vs baseline: 3.2857x; 3.2857x over previous
#include <cuda_runtime.h>
#include <cuda_bf16.h>
#include <cstdint>
#include <math.h>

#define TT 128
#define BB 512
#define DD 300
#define DPAD 320
#define HH 512
#define G3 1536

#define SO_AHI 0
#define SO_ALO 16384
#define SO_BHI 32768
#define SO_BLO 57344
#define STAGE  81920
#define SMEM_SZ (2 * STAGE)

__device__ __forceinline__ uint32_t smem_u32(const void* p) {
    uint32_t a;
    asm("{ .reg .u64 t; cvta.to.shared.u64 t, %1; cvt.u32.u64 %0, t; }" : "=r"(a) : "l"(p));
    return a;
}
__device__ __forceinline__ void cp16(uint32_t s, const void* g) {
    asm volatile("cp.async.cg.shared.global [%0], [%1], 16;" :: "r"(s), "l"(g));
}
__device__ __forceinline__ void ldm4(uint32_t* r, uint32_t a) {
    asm volatile("ldmatrix.sync.aligned.m8n8.x4.shared.b16 {%0,%1,%2,%3}, [%4];"
                 : "=r"(r[0]), "=r"(r[1]), "=r"(r[2]), "=r"(r[3]) : "r"(a));
}
__device__ __forceinline__ void mma16816(float* c, const uint32_t* a, const uint32_t* b) {
    asm volatile("mma.sync.aligned.m16n8k16.row.col.f32.bf16.bf16.f32 "
        "{%0,%1,%2,%3}, {%4,%5,%6,%7}, {%8,%9}, {%0,%1,%2,%3};"
        : "+f"(c[0]), "+f"(c[1]), "+f"(c[2]), "+f"(c[3])
        : "r"(a[0]), "r"(a[1]), "r"(a[2]), "r"(a[3]), "r"(b[0]), "r"(b[1]));
}
__device__ __forceinline__ uint32_t swz(uint32_t o) { return o ^ ((o >> 3) & 0x70); }
__device__ __forceinline__ float sigmoidf_(float x) { return 1.f / (1.f + expf(-x)); }

__device__ __align__(16) __nv_bfloat16 g_xhi[(size_t)TT * BB * DPAD];
__device__ __align__(16) __nv_bfloat16 g_xlo[(size_t)TT * BB * DPAD];
__device__ __align__(16) __nv_bfloat16 g_Wih0[2][2][(size_t)G3 * DPAD];
__device__ __align__(16) __nv_bfloat16 g_Wih[2][2][2][(size_t)G3 * HH];
__device__ __align__(16) __nv_bfloat16 g_Whh[2][3][2][(size_t)G3 * HH];
__device__ float g_bih[2][3][G3];
__device__ float g_bhh[2][3][G3];
__device__ __align__(16) __nv_bfloat16 g_hhi[2][(size_t)TT * BB * HH];
__device__ __align__(16) __nv_bfloat16 g_hlo[2][(size_t)TT * BB * HH];
__device__ __align__(16) float g_gi[2][(size_t)TT * BB * G3];

// ---------------- prep: fp32 -> bf16 hi/lo, gate-permute rows ----------------
// dest row r: rem=r%192, srcrow = (rem>>6)*512 + (r/192)*64 + (rem&63)
__global__ void prep_x(const float* __restrict__ src) {
    const size_t total = (size_t)TT * BB * DPAD;
    for (size_t i = (size_t)blockIdx.x * blockDim.x + threadIdx.x; i < total;
         i += (size_t)gridDim.x * blockDim.x) {
        int r = (int)(i / DPAD), k = (int)(i % DPAD);
        float v = (k < DD) ? src[(size_t)r * DD + k] : 0.f;
        __nv_bfloat16 h = __float2bfloat16(v);
        g_xhi[i] = h; g_xlo[i] = __float2bfloat16(v - __bfloat162float(h));
    }
}
__global__ void prep_w(const float* __restrict__ src, int dir, int kind, int l) {
    int K, Kpad; __nv_bfloat16 *hi, *lo;
    if (kind == 0)      { K = DD; Kpad = DPAD; hi = g_Wih0[dir][0]; lo = g_Wih0[dir][1]; }
    else if (kind == 1) { K = HH; Kpad = HH;   hi = g_Wih[dir][l][0]; lo = g_Wih[dir][l][1]; }
    else                { K = HH; Kpad = HH;   hi = g_Whh[dir][l][0]; lo = g_Whh[dir][l][1]; }
    const size_t total = (size_t)G3 * Kpad;
    for (size_t i = (size_t)blockIdx.x * blockDim.x + threadIdx.x; i < total;
         i += (size_t)gridDim.x * blockDim.x) {
        int r = (int)(i / Kpad), k = (int)(i % Kpad);
        int rem = r % 192;
        int sr = (rem >> 6) * HH + (r / 192) * 64 + (rem & 63);
        float v = (k < K) ? src[(size_t)sr * K + k] : 0.f;
        __nv_bfloat16 h = __float2bfloat16(v);
        hi[i] = h; lo[i] = __float2bfloat16(v - __bfloat162float(h));
    }
}
__global__ void prep_b(const float* __restrict__ src, int dir, int which, int l) {
    int r = blockIdx.x * blockDim.x + threadIdx.x;
    if (r < G3) {
        int rem = r % 192;
        float v = src[(rem >> 6) * HH + (r / 192) * 64 + (rem & 63)];
        if (which == 0) g_bih[dir][l][r] = v; else g_bhh[dir][l][r] = v;
    }
}

// ---------------- mainloop pieces ----------------
__device__ __forceinline__ void load_tile(
    uint32_t sbuf, const char* Ah, const char* Al, size_t lda,
    const char* Wh, const char* Wl, size_t ldw, int kt, int tid)
{
    const size_t kb = (size_t)kt * 128;
    for (int i = tid; i < 1024; i += 256) {
        int r = i >> 3, ch = (i & 7) * 16;
        uint32_t so = swz((uint32_t)(r * 128 + ch));
        const size_t go = (size_t)r * lda + kb + ch;
        cp16(sbuf + SO_AHI + so, Ah + go);
        cp16(sbuf + SO_ALO + so, Al + go);
    }
    for (int i = tid; i < 1536; i += 256) {
        int r = i >> 3, ch = (i & 7) * 16;
        uint32_t so = swz((uint32_t)(r * 128 + ch));
        const size_t go = (size_t)r * ldw + kb + ch;
        cp16(sbuf + SO_BHI + so, Wh + go);
        cp16(sbuf + SO_BLO + so, Wl + go);
    }
    asm volatile("cp.async.commit_group;" ::: "memory");
}

__device__ __forceinline__ void compute_tile(
    uint32_t sbuf, int wm, int wn, int lane, float (&acc)[2][3][4][4])
{
    const int arow = wm * 32 + (lane & 15);
    const int acolsel = (lane >> 4) * 16;
    const int mat = lane >> 3;
    const int brow_in = (mat >> 1) * 8 + (lane & 7);
    const int bcol = (mat & 1) * 16;
    #pragma unroll
    for (int kk = 0; kk < 4; kk++) {
        uint32_t ah[2][4], al[2][4];
        #pragma unroll
        for (int mt = 0; mt < 2; mt++) {
            uint32_t o = swz((uint32_t)((arow + mt * 16) * 128 + kk * 32 + acolsel));
            ldm4(ah[mt], sbuf + SO_AHI + o);
            ldm4(al[mt], sbuf + SO_ALO + o);
        }
        #pragma unroll
        for (int g = 0; g < 3; g++) {
            #pragma unroll
            for (int p = 0; p < 2; p++) {
                uint32_t o = swz((uint32_t)((g * 64 + wn * 32 + p * 16 + brow_in) * 128
                                            + kk * 32 + bcol));
                uint32_t bh[4], bl[4];
                ldm4(bh, sbuf + SO_BHI + o);
                ldm4(bl, sbuf + SO_BLO + o);
                #pragma unroll
                for (int mt = 0; mt < 2; mt++) {
                    #pragma unroll
                    for (int q = 0; q < 2; q++) {
                        float* c = acc[mt][g][p * 2 + q];
                        mma16816(c, ah[mt], &bh[q * 2]);
                        mma16816(c, ah[mt], &bl[q * 2]);
                        mma16816(c, al[mt], &bh[q * 2]);
                    }
                }
            }
        }
    }
}

__device__ __forceinline__ void run_mainloop(
    uint32_t sb, const char* Ah, const char* Al, size_t lda,
    const char* Wh, const char* Wl, size_t ldw,
    int NK, int tid, int wm, int wn, int lane, float (&acc)[2][3][4][4])
{
    load_tile(sb, Ah, Al, lda, Wh, Wl, ldw, 0, tid);
    for (int kt = 0; kt < NK; kt++) {
        if (kt + 1 < NK) {
            load_tile(sb + ((kt + 1) & 1) * STAGE, Ah, Al, lda, Wh, Wl, ldw, kt + 1, tid);
            asm volatile("cp.async.wait_group 1;" ::: "memory");
        } else {
            asm volatile("cp.async.wait_group 0;" ::: "memory");
        }
        __syncthreads();
        compute_tile(sb + (kt & 1) * STAGE, wm, wn, lane, acc);
        __syncthreads();
    }
}

// ---------------- gi GEMM: grid (8, 512, 2) ----------------
__global__ __launch_bounds__(256) void gi_mma(int l)
{
    extern __shared__ char smem[];
    const uint32_t sb = smem_u32(smem);
    const int tid = threadIdx.x, lane = tid & 31, wid = tid >> 5;
    const int wm = wid & 3, wn = wid >> 2;
    const int dir = blockIdx.z, nblk = blockIdx.x, m0 = blockIdx.y * 128;

    const __nv_bfloat16 *Ah, *Al, *Wh, *Wl;
    int ld, NK; size_t arow0;
    if (l == 0) {
        ld = DPAD; NK = 5;
        int t = m0 / BB, tt = dir ? (TT - 1 - t) : t;
        arow0 = (size_t)tt * BB + (m0 % BB);
        Ah = g_xhi; Al = g_xlo; Wh = g_Wih0[dir][0]; Wl = g_Wih0[dir][1];
    } else {
        ld = HH; NK = 8; arow0 = m0;
        Ah = g_hhi[dir]; Al = g_hlo[dir];
        Wh = g_Wih[dir][l - 1][0]; Wl = g_Wih[dir][l - 1][1];
    }
    const size_t ldb = (size_t)ld * 2;
    const char* Ahb = (const char*)(Ah + arow0 * ld);
    const char* Alb = (const char*)(Al + arow0 * ld);
    const char* Whb = (const char*)(Wh + (size_t)nblk * 192 * ld);
    const char* Wlb = (const char*)(Wl + (size_t)nblk * 192 * ld);

    float acc[2][3][4][4];
    #pragma unroll
    for (int a = 0; a < 2; a++)
        #pragma unroll
        for (int b = 0; b < 3; b++)
            #pragma unroll
            for (int c = 0; c < 4; c++)
                #pragma unroll
                for (int d = 0; d < 4; d++) acc[a][b][c][d] = 0.f;

    run_mainloop(sb, Ahb, Alb, ldb, Whb, Wlb, ldb, NK, tid, wm, wn, lane, acc);

    float* gout = g_gi[dir];
    const float* bias = g_bih[dir][l];
    #pragma unroll
    for (int mt = 0; mt < 2; mt++) {
        const int r0 = m0 + wm * 32 + mt * 16 + (lane >> 2);
        #pragma unroll
        for (int g = 0; g < 3; g++)
            #pragma unroll
            for (int nt = 0; nt < 4; nt++) {
                const int col = nblk * 192 + g * 64 + wn * 32 + nt * 8 + (lane & 3) * 2;
                const float b0 = bias[col], b1 = bias[col + 1];
                const float* c = acc[mt][g][nt];
                *(float2*)(gout + (size_t)r0 * G3 + col) = make_float2(c[0] + b0, c[1] + b1);
                *(float2*)(gout + (size_t)(r0 + 8) * G3 + col) = make_float2(c[2] + b0, c[3] + b1);
            }
    }
}

// ---------------- fused recurrent step: grid (8, 4, 2) ----------------
__global__ __launch_bounds__(256) void gru_mma(int t, int l)
{
    extern __shared__ char smem[];
    const uint32_t sb = smem_u32(smem);
    const int tid = threadIdx.x, lane = tid & 31, wid = tid >> 5;
    const int wm = wid & 3, wn = wid >> 2;
    const int dir = blockIdx.z, nblk = blockIdx.x, m0 = blockIdx.y * 128;

    float acc[2][3][4][4];
    #pragma unroll
    for (int a = 0; a < 2; a++)
        #pragma unroll
        for (int b = 0; b < 3; b++)
            #pragma unroll
            for (int c = 0; c < 4; c++)
                #pragma unroll
                for (int d = 0; d < 4; d++) acc[a][b][c][d] = 0.f;

    if (t > 0) {
        const size_t arow0 = (size_t)(t - 1) * BB + m0;
        const char* Ahb = (const char*)(g_hhi[dir] + arow0 * HH);
        const char* Alb = (const char*)(g_hlo[dir] + arow0 * HH);
        const char* Whb = (const char*)(g_Whh[dir][l][0] + (size_t)nblk * 192 * HH);
        const char* Wlb = (const char*)(g_Whh[dir][l][1] + (size_t)nblk * 192 * HH);
        run_mainloop(sb, Ahb, Alb, HH * 2, Whb, Wlb, HH * 2, 8, tid, wm, wn, lane, acc);
    }

    const float* giP = g_gi[dir] + (size_t)t * BB * G3;
    const float* bh = g_bhh[dir][l];
    const __nv_bfloat16* Phi = g_hhi[dir] + (size_t)(t - 1) * BB * HH;
    const __nv_bfloat16* Plo = g_hlo[dir] + (size_t)(t - 1) * BB * HH;
    __nv_bfloat16* Ohi = g_hhi[dir] + (size_t)t * BB * HH;
    __nv_bfloat16* Olo = g_hlo[dir] + (size_t)t * BB * HH;

    #pragma unroll
    for (int mt = 0; mt < 2; mt++)
        #pragma unroll
        for (int nt = 0; nt < 4; nt++) {
            const int hl = wn * 32 + nt * 8 + (lane & 3) * 2;
            const int cr = nblk * 192 + hl;
            const int hc = nblk * 64 + hl;
            const float* c_r = acc[mt][0][nt];
            const float* c_z = acc[mt][1][nt];
            const float* c_n = acc[mt][2][nt];
            const float bhr0 = bh[cr], bhr1 = bh[cr + 1];
            const float bhz0 = bh[cr + 64], bhz1 = bh[cr + 65];
            const float bhn0 = bh[cr + 128], bhn1 = bh[cr + 129];
            #pragma unroll
            for (int hf = 0; hf < 2; hf++) {
                const int m = m0 + wm * 32 + mt * 16 + (lane >> 2) + hf * 8;
                const float* gim = giP + (size_t)m * G3;
                const float2 gr = *(const float2*)(gim + cr);
                const float2 gz = *(const float2*)(gim + cr + 64);
                const float2 gn = *(const float2*)(gim + cr + 128);
                float hp0 = 0.f, hp1 = 0.f;
                if (t > 0) {
                    __nv_bfloat162 ph = *(const __nv_bfloat162*)(Phi + (size_t)m * HH + hc);
                    __nv_bfloat162 pl = *(const __nv_bfloat162*)(Plo + (size_t)m * HH + hc);
                    hp0 = __bfloat162float(ph.x) + __bfloat162float(pl.x);
                    hp1 = __bfloat162float(ph.y) + __bfloat162float(pl.y);
                }
                const float rg0 = sigmoidf_(gr.x + bhr0 + c_r[hf * 2 + 0]);
                const float rg1 = sigmoidf_(gr.y + bhr1 + c_r[hf * 2 + 1]);
                const float zg0 = sigmoidf_(gz.x + bhz0 + c_z[hf * 2 + 0]);
                const float zg1 = sigmoidf_(gz.y + bhz1 + c_z[hf * 2 + 1]);
                const float ng0 = tanhf(gn.x + rg0 * (c_n[hf * 2 + 0] + bhn0));
                const float ng1 = tanhf(gn.y + rg1 * (c_n[hf * 2 + 1] + bhn1));
                const float h0 = (1.f - zg0) * ng0 + zg0 * hp0;
                const float h1 = (1.f - zg1) * ng1 + zg1 * hp1;
                __nv_bfloat162 hhi, hlo;
                hhi.x = __float2bfloat16(h0);
                hhi.y = __float2bfloat16(h1);
                hlo.x = __float2bfloat16(h0 - __bfloat162float(hhi.x));
                hlo.y = __float2bfloat16(h1 - __bfloat162float(hhi.y));
                *(__nv_bfloat162*)(Ohi + (size_t)m * HH + hc) = hhi;
                *(__nv_bfloat162*)(Olo + (size_t)m * HH + hc) = hlo;
            }
        }
}

// ---------------- projection ----------------
__global__ __launch_bounds__(256) void proj_kernel(
    const float* __restrict__ Wmu, const float* __restrict__ bmu,
    const float* __restrict__ Wlv, const float* __restrict__ blv,
    float* __restrict__ out)
{
    __shared__ float As[16][66];
    __shared__ float Bs[16][66];
    const int which = blockIdx.z;
    const float* W = which ? Wlv : Wmu;
    const float* bias = which ? blv : bmu;
    const int n0 = blockIdx.x * 64, m0 = blockIdx.y * 64;
    const __nv_bfloat16* hfh = g_hhi[0] + ((size_t)(TT - 1) * BB + m0) * HH;
    const __nv_bfloat16* hfl = g_hlo[0] + ((size_t)(TT - 1) * BB + m0) * HH;
    const __nv_bfloat16* hbh = g_hhi[1] + ((size_t)(TT - 1) * BB + m0) * HH;
    const __nv_bfloat16* hbl = g_hlo[1] + ((size_t)(TT - 1) * BB + m0) * HH;
    const int tid = threadIdx.x, tx = tid & 15, ty = tid >> 4;
    float acc[4][4];
    #pragma unroll
    for (int i = 0; i < 4; i++)
        #pragma unroll
        for (int j = 0; j < 4; j++) acc[i][j] = 0.f;

    for (int k0 = 0; k0 < 2 * HH; k0 += 16) {
        #pragma unroll
        for (int i = 0; i < 4; i++) {
            const int e = tid + i * 256;
            const int kk = e & 15, mm = e >> 4;
            const int k = k0 + kk;
            float a;
            if (k < HH) a = __bfloat162float(hfh[(size_t)mm * HH + k]) + __bfloat162float(hfl[(size_t)mm * HH + k]);
            else        a = __bfloat162float(hbh[(size_t)mm * HH + k - HH]) + __bfloat162float(hbl[(size_t)mm * HH + k - HH]);
            As[kk][mm] = a;
            Bs[kk][mm] = W[(size_t)(n0 + mm) * (2 * HH) + k];
        }
        __syncthreads();
        #pragma unroll
        for (int kk = 0; kk < 16; kk++) {
            float a[4], b[4];
            #pragma unroll
            for (int i = 0; i < 4; i++) a[i] = As[kk][ty * 4 + i];
            #pragma unroll
            for (int j = 0; j < 4; j++) b[j] = Bs[kk][tx * 4 + j];
            #pragma unroll
            for (int i = 0; i < 4; i++)
                #pragma unroll
                for (int j = 0; j < 4; j++) acc[i][j] += a[i] * b[j];
        }
        __syncthreads();
    }
    #pragma unroll
    for (int i = 0; i < 4; i++) {
        const int m = m0 + ty * 4 + i;
        #pragma unroll
        for (int j = 0; j < 4; j++) {
            const int n = n0 + tx * 4 + j;
            out[(size_t)which * BB * HH + (size_t)m * HH + n] = acc[i][j] + bias[n];
        }
    }
}

extern "C" void kernel_launch(void* const* d_in, const int* in_sizes, int n_in,
                              void* d_out, int out_size)
{
    (void)in_sizes; (void)n_in; (void)out_size;
    const float* x       = (const float*)d_in[0];
    const float* fw_Wih0 = (const float*)d_in[2];
    const float* fw_Whh0 = (const float*)d_in[3];
    const float* fw_bih0 = (const float*)d_in[4];
    const float* fw_bhh0 = (const float*)d_in[5];
    const float* fw_Wih  = (const float*)d_in[6];
    const float* fw_Whh  = (const float*)d_in[7];
    const float* fw_bih  = (const float*)d_in[8];
    const float* fw_bhh  = (const float*)d_in[9];
    const float* bw_Wih0 = (const float*)d_in[10];
    const float* bw_Whh0 = (const float*)d_in[11];
    const float* bw_bih0 = (const float*)d_in[12];
    const float* bw_bhh0 = (const float*)d_in[13];
    const float* bw_Wih  = (const float*)d_in[14];
    const float* bw_Whh  = (const float*)d_in[15];
    const float* bw_bih  = (const float*)d_in[16];
    const float* bw_bhh  = (const float*)d_in[17];
    const float* W_mu    = (const float*)d_in[18];
    const float* b_mu    = (const float*)d_in[19];
    const float* W_lv    = (const float*)d_in[20];
    const float* b_lv    = (const float*)d_in[21];
    float* out = (float*)d_out;

    cudaFuncSetAttribute(gi_mma,  cudaFuncAttributeMaxDynamicSharedMemorySize, SMEM_SZ);
    cudaFuncSetAttribute(gru_mma, cudaFuncAttributeMaxDynamicSharedMemorySize, SMEM_SZ);

    prep_x<<<2048, 256>>>(x);
    prep_w<<<256, 256>>>(fw_Wih0, 0, 0, 0);
    prep_w<<<256, 256>>>(bw_Wih0, 1, 0, 0);
    for (int l = 0; l < 2; l++) {
        prep_w<<<512, 256>>>(fw_Wih + (size_t)l * G3 * HH, 0, 1, l);
        prep_w<<<512, 256>>>(bw_Wih + (size_t)l * G3 * HH, 1, 1, l);
    }
    prep_w<<<512, 256>>>(fw_Whh0, 0, 2, 0);
    prep_w<<<512, 256>>>(bw_Whh0, 1, 2, 0);
    for (int l = 1; l < 3; l++) {
        prep_w<<<512, 256>>>(fw_Whh + (size_t)(l - 1) * G3 * HH, 0, 2, l);
        prep_w<<<512, 256>>>(bw_Whh + (size_t)(l - 1) * G3 * HH, 1, 2, l);
    }
    prep_b<<<6, 256>>>(fw_bih0, 0, 0, 0);
    prep_b<<<6, 256>>>(bw_bih0, 1, 0, 0);
    prep_b<<<6, 256>>>(fw_bhh0, 0, 1, 0);
    prep_b<<<6, 256>>>(bw_bhh0, 1, 1, 0);
    for (int l = 1; l < 3; l++) {
        prep_b<<<6, 256>>>(fw_bih + (size_t)(l - 1) * G3, 0, 0, l);
        prep_b<<<6, 256>>>(bw_bih + (size_t)(l - 1) * G3, 1, 0, l);
        prep_b<<<6, 256>>>(fw_bhh + (size_t)(l - 1) * G3, 0, 1, l);
        prep_b<<<6, 256>>>(bw_bhh + (size_t)(l - 1) * G3, 1, 1, l);
    }

    const dim3 ggi(8, (TT * BB) / 128, 2);
    const dim3 gst(8, 4, 2);
    for (int l = 0; l < 3; l++) {
        gi_mma<<<ggi, 256, SMEM_SZ>>>(l);
        for (int t = 0; t < TT; t++)
            gru_mma<<<gst, 256, SMEM_SZ>>>(t, l);
    }
    proj_kernel<<<dim3(HH / 64, BB / 64, 2), 256>>>(W_mu, b_mu, W_lv, b_lv, out);
}

// round 5
// speedup vs baseline: 4.7411x; 1.4429x over previous
#include <cuda_runtime.h>
#include <cuda_bf16.h>
#include <cstdint>
#include <math.h>

#define TT 128
#define BB 512
#define DD 300
#define DPAD 320
#define HH 512
#define G3 1536

// gi kernel smem layout (CTA tile 128x192)
#define SO_AHI 0
#define SO_ALO 16384
#define SO_BHI 32768
#define SO_BLO 57344
#define STAGE  81920
#define SMEM_GI (2 * STAGE)

// gru kernel smem layout (CTA tile 64x192)
#define GSO_AHI 0
#define GSO_ALO 8192
#define GSO_BHI 16384
#define GSO_BLO 40960
#define GSTAGE  65536
#define SMEM_GRU (2 * GSTAGE)

__device__ __forceinline__ uint32_t smem_u32(const void* p) {
    uint32_t a;
    asm("{ .reg .u64 t; cvta.to.shared.u64 t, %1; cvt.u32.u64 %0, t; }" : "=r"(a) : "l"(p));
    return a;
}
__device__ __forceinline__ void cp16(uint32_t s, const void* g) {
    asm volatile("cp.async.cg.shared.global [%0], [%1], 16;" :: "r"(s), "l"(g));
}
__device__ __forceinline__ void ldm4(uint32_t* r, uint32_t a) {
    asm volatile("ldmatrix.sync.aligned.m8n8.x4.shared.b16 {%0,%1,%2,%3}, [%4];"
                 : "=r"(r[0]), "=r"(r[1]), "=r"(r[2]), "=r"(r[3]) : "r"(a));
}
__device__ __forceinline__ void mma16816(float* c, const uint32_t* a, const uint32_t* b) {
    asm volatile("mma.sync.aligned.m16n8k16.row.col.f32.bf16.bf16.f32 "
        "{%0,%1,%2,%3}, {%4,%5,%6,%7}, {%8,%9}, {%0,%1,%2,%3};"
        : "+f"(c[0]), "+f"(c[1]), "+f"(c[2]), "+f"(c[3])
        : "r"(a[0]), "r"(a[1]), "r"(a[2]), "r"(a[3]), "r"(b[0]), "r"(b[1]));
}
__device__ __forceinline__ uint32_t swz(uint32_t o) { return o ^ ((o >> 3) & 0x70); }
__device__ __forceinline__ float sigmoidf_(float x) { return 1.f / (1.f + expf(-x)); }

__device__ __align__(16) __nv_bfloat16 g_xhi[(size_t)TT * BB * DPAD];
__device__ __align__(16) __nv_bfloat16 g_xlo[(size_t)TT * BB * DPAD];
__device__ __align__(16) __nv_bfloat16 g_Wih0[2][2][(size_t)G3 * DPAD];
__device__ __align__(16) __nv_bfloat16 g_Wih[2][2][2][(size_t)G3 * HH];
__device__ __align__(16) __nv_bfloat16 g_Whh[2][3][2][(size_t)G3 * HH];
__device__ float g_bih[2][3][G3];
__device__ float g_bhh[2][3][G3];
__device__ __align__(16) __nv_bfloat16 g_hhi[2][(size_t)TT * BB * HH];
__device__ __align__(16) __nv_bfloat16 g_hlo[2][(size_t)TT * BB * HH];
__device__ __align__(16) float g_gi[2][(size_t)TT * BB * G3];

// ---------------- prep: fp32 -> bf16 hi/lo, gate-permute rows ----------------
__global__ void prep_x(const float* __restrict__ src) {
    const size_t total = (size_t)TT * BB * DPAD;
    for (size_t i = (size_t)blockIdx.x * blockDim.x + threadIdx.x; i < total;
         i += (size_t)gridDim.x * blockDim.x) {
        int r = (int)(i / DPAD), k = (int)(i % DPAD);
        float v = (k < DD) ? src[(size_t)r * DD + k] : 0.f;
        __nv_bfloat16 h = __float2bfloat16(v);
        g_xhi[i] = h; g_xlo[i] = __float2bfloat16(v - __bfloat162float(h));
    }
}
__global__ void prep_w(const float* __restrict__ src, int dir, int kind, int l) {
    int K, Kpad; __nv_bfloat16 *hi, *lo;
    if (kind == 0)      { K = DD; Kpad = DPAD; hi = g_Wih0[dir][0]; lo = g_Wih0[dir][1]; }
    else if (kind == 1) { K = HH; Kpad = HH;   hi = g_Wih[dir][l][0]; lo = g_Wih[dir][l][1]; }
    else                { K = HH; Kpad = HH;   hi = g_Whh[dir][l][0]; lo = g_Whh[dir][l][1]; }
    const size_t total = (size_t)G3 * Kpad;
    for (size_t i = (size_t)blockIdx.x * blockDim.x + threadIdx.x; i < total;
         i += (size_t)gridDim.x * blockDim.x) {
        int r = (int)(i / Kpad), k = (int)(i % Kpad);
        int rem = r % 192;
        int sr = (rem >> 6) * HH + (r / 192) * 64 + (rem & 63);
        float v = (k < K) ? src[(size_t)sr * K + k] : 0.f;
        __nv_bfloat16 h = __float2bfloat16(v);
        hi[i] = h; lo[i] = __float2bfloat16(v - __bfloat162float(h));
    }
}
__global__ void prep_b(const float* __restrict__ src, int dir, int which, int l) {
    int r = blockIdx.x * blockDim.x + threadIdx.x;
    if (r < G3) {
        int rem = r % 192;
        float v = src[(rem >> 6) * HH + (r / 192) * 64 + (rem & 63)];
        if (which == 0) g_bih[dir][l][r] = v; else g_bhh[dir][l][r] = v;
    }
}

// ================= gi GEMM path (CTA 128x192) =================
__device__ __forceinline__ void load_tile(
    uint32_t sbuf, const char* Ah, const char* Al, size_t lda,
    const char* Wh, const char* Wl, size_t ldw, int kt, int tid)
{
    const size_t kb = (size_t)kt * 128;
    for (int i = tid; i < 1024; i += 256) {
        int r = i >> 3, ch = (i & 7) * 16;
        uint32_t so = swz((uint32_t)(r * 128 + ch));
        const size_t go = (size_t)r * lda + kb + ch;
        cp16(sbuf + SO_AHI + so, Ah + go);
        cp16(sbuf + SO_ALO + so, Al + go);
    }
    for (int i = tid; i < 1536; i += 256) {
        int r = i >> 3, ch = (i & 7) * 16;
        uint32_t so = swz((uint32_t)(r * 128 + ch));
        const size_t go = (size_t)r * ldw + kb + ch;
        cp16(sbuf + SO_BHI + so, Wh + go);
        cp16(sbuf + SO_BLO + so, Wl + go);
    }
    asm volatile("cp.async.commit_group;" ::: "memory");
}

__device__ __forceinline__ void compute_tile(
    uint32_t sbuf, int wm, int wn, int lane, float (&acc)[2][3][4][4])
{
    const int arow = wm * 32 + (lane & 15);
    const int acolsel = (lane >> 4) * 16;
    const int mat = lane >> 3;
    const int brow_in = (mat >> 1) * 8 + (lane & 7);
    const int bcol = (mat & 1) * 16;
    #pragma unroll
    for (int kk = 0; kk < 4; kk++) {
        uint32_t ah[2][4], al[2][4];
        #pragma unroll
        for (int mt = 0; mt < 2; mt++) {
            uint32_t o = swz((uint32_t)((arow + mt * 16) * 128 + kk * 32 + acolsel));
            ldm4(ah[mt], sbuf + SO_AHI + o);
            ldm4(al[mt], sbuf + SO_ALO + o);
        }
        #pragma unroll
        for (int g = 0; g < 3; g++) {
            #pragma unroll
            for (int p = 0; p < 2; p++) {
                uint32_t o = swz((uint32_t)((g * 64 + wn * 32 + p * 16 + brow_in) * 128
                                            + kk * 32 + bcol));
                uint32_t bh[4], bl[4];
                ldm4(bh, sbuf + SO_BHI + o);
                ldm4(bl, sbuf + SO_BLO + o);
                #pragma unroll
                for (int mt = 0; mt < 2; mt++) {
                    #pragma unroll
                    for (int q = 0; q < 2; q++) {
                        float* c = acc[mt][g][p * 2 + q];
                        mma16816(c, ah[mt], &bh[q * 2]);
                        mma16816(c, ah[mt], &bl[q * 2]);
                        mma16816(c, al[mt], &bh[q * 2]);
                    }
                }
            }
        }
    }
}

__global__ __launch_bounds__(256) void gi_mma(int l)
{
    extern __shared__ char smem[];
    const uint32_t sb = smem_u32(smem);
    const int tid = threadIdx.x, lane = tid & 31, wid = tid >> 5;
    const int wm = wid & 3, wn = wid >> 2;
    const int dir = blockIdx.z, nblk = blockIdx.x, m0 = blockIdx.y * 128;

    const __nv_bfloat16 *Ah, *Al, *Wh, *Wl;
    int ld, NK; size_t arow0;
    if (l == 0) {
        ld = DPAD; NK = 5;
        int t = m0 / BB, tt = dir ? (TT - 1 - t) : t;
        arow0 = (size_t)tt * BB + (m0 % BB);
        Ah = g_xhi; Al = g_xlo; Wh = g_Wih0[dir][0]; Wl = g_Wih0[dir][1];
    } else {
        ld = HH; NK = 8; arow0 = m0;
        Ah = g_hhi[dir]; Al = g_hlo[dir];
        Wh = g_Wih[dir][l - 1][0]; Wl = g_Wih[dir][l - 1][1];
    }
    const size_t ldb = (size_t)ld * 2;
    const char* Ahb = (const char*)(Ah + arow0 * ld);
    const char* Alb = (const char*)(Al + arow0 * ld);
    const char* Whb = (const char*)(Wh + (size_t)nblk * 192 * ld);
    const char* Wlb = (const char*)(Wl + (size_t)nblk * 192 * ld);

    float acc[2][3][4][4];
    #pragma unroll
    for (int a = 0; a < 2; a++)
        #pragma unroll
        for (int b = 0; b < 3; b++)
            #pragma unroll
            for (int c = 0; c < 4; c++)
                #pragma unroll
                for (int d = 0; d < 4; d++) acc[a][b][c][d] = 0.f;

    load_tile(sb, Ahb, Alb, ldb, Whb, Wlb, ldb, 0, tid);
    for (int kt = 0; kt < NK; kt++) {
        if (kt + 1 < NK) {
            load_tile(sb + ((kt + 1) & 1) * STAGE, Ahb, Alb, ldb, Whb, Wlb, ldb, kt + 1, tid);
            asm volatile("cp.async.wait_group 1;" ::: "memory");
        } else {
            asm volatile("cp.async.wait_group 0;" ::: "memory");
        }
        __syncthreads();
        compute_tile(sb + (kt & 1) * STAGE, wm, wn, lane, acc);
        __syncthreads();
    }

    float* gout = g_gi[dir];
    const float* bias = g_bih[dir][l];
    #pragma unroll
    for (int mt = 0; mt < 2; mt++) {
        const int r0 = m0 + wm * 32 + mt * 16 + (lane >> 2);
        #pragma unroll
        for (int g = 0; g < 3; g++)
            #pragma unroll
            for (int nt = 0; nt < 4; nt++) {
                const int col = nblk * 192 + g * 64 + wn * 32 + nt * 8 + (lane & 3) * 2;
                const float b0 = bias[col], b1 = bias[col + 1];
                const float* c = acc[mt][g][nt];
                *(float2*)(gout + (size_t)r0 * G3 + col) = make_float2(c[0] + b0, c[1] + b1);
                *(float2*)(gout + (size_t)(r0 + 8) * G3 + col) = make_float2(c[2] + b0, c[3] + b1);
            }
    }
}

// ================= fused recurrent step (CTA 64x192, grid (8,8,2) = 128 CTAs) =================
__device__ __forceinline__ void load_tile_gru(
    uint32_t sbuf, const char* Ah, const char* Al,
    const char* Wh, const char* Wl, int kt, int tid)
{
    const size_t kb = (size_t)kt * 128;
    const size_t ldb = HH * 2;
    for (int i = tid; i < 512; i += 256) {
        int r = i >> 3, ch = (i & 7) * 16;
        uint32_t so = swz((uint32_t)(r * 128 + ch));
        const size_t go = (size_t)r * ldb + kb + ch;
        cp16(sbuf + GSO_AHI + so, Ah + go);
        cp16(sbuf + GSO_ALO + so, Al + go);
    }
    for (int i = tid; i < 1536; i += 256) {
        int r = i >> 3, ch = (i & 7) * 16;
        uint32_t so = swz((uint32_t)(r * 128 + ch));
        const size_t go = (size_t)r * ldb + kb + ch;
        cp16(sbuf + GSO_BHI + so, Wh + go);
        cp16(sbuf + GSO_BLO + so, Wl + go);
    }
    asm volatile("cp.async.commit_group;" ::: "memory");
}

__device__ __forceinline__ void compute_tile_gru(
    uint32_t sbuf, int wm, int wn, int lane, float (&acc)[2][3][2][4])
{
    const int arow = wm * 32 + (lane & 15);
    const int acolsel = (lane >> 4) * 16;
    const int mat = lane >> 3;
    const int brow_in = (mat >> 1) * 8 + (lane & 7);
    const int bcol = (mat & 1) * 16;
    #pragma unroll
    for (int kk = 0; kk < 4; kk++) {
        uint32_t ah[2][4], al[2][4];
        #pragma unroll
        for (int mt = 0; mt < 2; mt++) {
            uint32_t o = swz((uint32_t)((arow + mt * 16) * 128 + kk * 32 + acolsel));
            ldm4(ah[mt], sbuf + GSO_AHI + o);
            ldm4(al[mt], sbuf + GSO_ALO + o);
        }
        #pragma unroll
        for (int g = 0; g < 3; g++) {
            uint32_t o = swz((uint32_t)((g * 64 + wn * 16 + brow_in) * 128 + kk * 32 + bcol));
            uint32_t bh[4], bl[4];
            ldm4(bh, sbuf + GSO_BHI + o);
            ldm4(bl, sbuf + GSO_BLO + o);
            #pragma unroll
            for (int mt = 0; mt < 2; mt++) {
                #pragma unroll
                for (int q = 0; q < 2; q++) {
                    float* c = acc[mt][g][q];
                    mma16816(c, ah[mt], &bh[q * 2]);
                    mma16816(c, ah[mt], &bl[q * 2]);
                    mma16816(c, al[mt], &bh[q * 2]);
                }
            }
        }
    }
}

__global__ __launch_bounds__(256) void gru_mma(int t, int l)
{
    extern __shared__ char smem[];
    const uint32_t sb = smem_u32(smem);
    const int tid = threadIdx.x, lane = tid & 31, wid = tid >> 5;
    const int wm = wid & 1, wn = wid >> 1;
    const int dir = blockIdx.z, nblk = blockIdx.x, m0 = blockIdx.y * 64;

    float acc[2][3][2][4];
    #pragma unroll
    for (int a = 0; a < 2; a++)
        #pragma unroll
        for (int b = 0; b < 3; b++)
            #pragma unroll
            for (int c = 0; c < 2; c++)
                #pragma unroll
                for (int d = 0; d < 4; d++) acc[a][b][c][d] = 0.f;

    if (t > 0) {
        const size_t arow0 = (size_t)(t - 1) * BB + m0;
        const char* Ahb = (const char*)(g_hhi[dir] + arow0 * HH);
        const char* Alb = (const char*)(g_hlo[dir] + arow0 * HH);
        const char* Whb = (const char*)(g_Whh[dir][l][0] + (size_t)nblk * 192 * HH);
        const char* Wlb = (const char*)(g_Whh[dir][l][1] + (size_t)nblk * 192 * HH);
        load_tile_gru(sb, Ahb, Alb, Whb, Wlb, 0, tid);
        for (int kt = 0; kt < 8; kt++) {
            if (kt + 1 < 8) {
                load_tile_gru(sb + ((kt + 1) & 1) * GSTAGE, Ahb, Alb, Whb, Wlb, kt + 1, tid);
                asm volatile("cp.async.wait_group 1;" ::: "memory");
            } else {
                asm volatile("cp.async.wait_group 0;" ::: "memory");
            }
            __syncthreads();
            compute_tile_gru(sb + (kt & 1) * GSTAGE, wm, wn, lane, acc);
            __syncthreads();
        }
    }

    const float* giP = g_gi[dir] + (size_t)t * BB * G3;
    const float* bh = g_bhh[dir][l];
    const __nv_bfloat16* Phi = g_hhi[dir] + (size_t)(t - 1) * BB * HH;
    const __nv_bfloat16* Plo = g_hlo[dir] + (size_t)(t - 1) * BB * HH;
    __nv_bfloat16* Ohi = g_hhi[dir] + (size_t)t * BB * HH;
    __nv_bfloat16* Olo = g_hlo[dir] + (size_t)t * BB * HH;

    #pragma unroll
    for (int mt = 0; mt < 2; mt++)
        #pragma unroll
        for (int q = 0; q < 2; q++) {
            const int hl = wn * 16 + q * 8 + (lane & 3) * 2;
            const int cr = nblk * 192 + hl;
            const int hc = nblk * 64 + hl;
            const float* c_r = acc[mt][0][q];
            const float* c_z = acc[mt][1][q];
            const float* c_n = acc[mt][2][q];
            const float bhr0 = bh[cr], bhr1 = bh[cr + 1];
            const float bhz0 = bh[cr + 64], bhz1 = bh[cr + 65];
            const float bhn0 = bh[cr + 128], bhn1 = bh[cr + 129];
            #pragma unroll
            for (int hf = 0; hf < 2; hf++) {
                const int m = m0 + wm * 32 + mt * 16 + (lane >> 2) + hf * 8;
                const float* gim = giP + (size_t)m * G3;
                const float2 gr = *(const float2*)(gim + cr);
                const float2 gz = *(const float2*)(gim + cr + 64);
                const float2 gn = *(const float2*)(gim + cr + 128);
                float hp0 = 0.f, hp1 = 0.f;
                if (t > 0) {
                    __nv_bfloat162 ph = *(const __nv_bfloat162*)(Phi + (size_t)m * HH + hc);
                    __nv_bfloat162 pl = *(const __nv_bfloat162*)(Plo + (size_t)m * HH + hc);
                    hp0 = __bfloat162float(ph.x) + __bfloat162float(pl.x);
                    hp1 = __bfloat162float(ph.y) + __bfloat162float(pl.y);
                }
                const float rg0 = sigmoidf_(gr.x + bhr0 + c_r[hf * 2 + 0]);
                const float rg1 = sigmoidf_(gr.y + bhr1 + c_r[hf * 2 + 1]);
                const float zg0 = sigmoidf_(gz.x + bhz0 + c_z[hf * 2 + 0]);
                const float zg1 = sigmoidf_(gz.y + bhz1 + c_z[hf * 2 + 1]);
                const float ng0 = tanhf(gn.x + rg0 * (c_n[hf * 2 + 0] + bhn0));
                const float ng1 = tanhf(gn.y + rg1 * (c_n[hf * 2 + 1] + bhn1));
                const float h0 = (1.f - zg0) * ng0 + zg0 * hp0;
                const float h1 = (1.f - zg1) * ng1 + zg1 * hp1;
                __nv_bfloat162 hhi, hlo;
                hhi.x = __float2bfloat16(h0);
                hhi.y = __float2bfloat16(h1);
                hlo.x = __float2bfloat16(h0 - __bfloat162float(hhi.x));
                hlo.y = __float2bfloat16(h1 - __bfloat162float(hhi.y));
                *(__nv_bfloat162*)(Ohi + (size_t)m * HH + hc) = hhi;
                *(__nv_bfloat162*)(Olo + (size_t)m * HH + hc) = hlo;
            }
        }
}

// ---------------- projection ----------------
__global__ __launch_bounds__(256) void proj_kernel(
    const float* __restrict__ Wmu, const float* __restrict__ bmu,
    const float* __restrict__ Wlv, const float* __restrict__ blv,
    float* __restrict__ out)
{
    __shared__ float As[16][66];
    __shared__ float Bs[16][66];
    const int which = blockIdx.z;
    const float* W = which ? Wlv : Wmu;
    const float* bias = which ? blv : bmu;
    const int n0 = blockIdx.x * 64, m0 = blockIdx.y * 64;
    const __nv_bfloat16* hfh = g_hhi[0] + ((size_t)(TT - 1) * BB + m0) * HH;
    const __nv_bfloat16* hfl = g_hlo[0] + ((size_t)(TT - 1) * BB + m0) * HH;
    const __nv_bfloat16* hbh = g_hhi[1] + ((size_t)(TT - 1) * BB + m0) * HH;
    const __nv_bfloat16* hbl = g_hlo[1] + ((size_t)(TT - 1) * BB + m0) * HH;
    const int tid = threadIdx.x, tx = tid & 15, ty = tid >> 4;
    float acc[4][4];
    #pragma unroll
    for (int i = 0; i < 4; i++)
        #pragma unroll
        for (int j = 0; j < 4; j++) acc[i][j] = 0.f;

    for (int k0 = 0; k0 < 2 * HH; k0 += 16) {
        #pragma unroll
        for (int i = 0; i < 4; i++) {
            const int e = tid + i * 256;
            const int kk = e & 15, mm = e >> 4;
            const int k = k0 + kk;
            float a;
            if (k < HH) a = __bfloat162float(hfh[(size_t)mm * HH + k]) + __bfloat162float(hfl[(size_t)mm * HH + k]);
            else        a = __bfloat162float(hbh[(size_t)mm * HH + k - HH]) + __bfloat162float(hbl[(size_t)mm * HH + k - HH]);
            As[kk][mm] = a;
            Bs[kk][mm] = W[(size_t)(n0 + mm) * (2 * HH) + k];
        }
        __syncthreads();
        #pragma unroll
        for (int kk = 0; kk < 16; kk++) {
            float a[4], b[4];
            #pragma unroll
            for (int i = 0; i < 4; i++) a[i] = As[kk][ty * 4 + i];
            #pragma unroll
            for (int j = 0; j < 4; j++) b[j] = Bs[kk][tx * 4 + j];
            #pragma unroll
            for (int i = 0; i < 4; i++)
                #pragma unroll
                for (int j = 0; j < 4; j++) acc[i][j] += a[i] * b[j];
        }
        __syncthreads();
    }
    #pragma unroll
    for (int i = 0; i < 4; i++) {
        const int m = m0 + ty * 4 + i;
        #pragma unroll
        for (int j = 0; j < 4; j++) {
            const int n = n0 + tx * 4 + j;
            out[(size_t)which * BB * HH + (size_t)m * HH + n] = acc[i][j] + bias[n];
        }
    }
}

extern "C" void kernel_launch(void* const* d_in, const int* in_sizes, int n_in,
                              void* d_out, int out_size)
{
    (void)in_sizes; (void)n_in; (void)out_size;
    const float* x       = (const float*)d_in[0];
    const float* fw_Wih0 = (const float*)d_in[2];
    const float* fw_Whh0 = (const float*)d_in[3];
    const float* fw_bih0 = (const float*)d_in[4];
    const float* fw_bhh0 = (const float*)d_in[5];
    const float* fw_Wih  = (const float*)d_in[6];
    const float* fw_Whh  = (const float*)d_in[7];
    const float* fw_bih  = (const float*)d_in[8];
    const float* fw_bhh  = (const float*)d_in[9];
    const float* bw_Wih0 = (const float*)d_in[10];
    const float* bw_Whh0 = (const float*)d_in[11];
    const float* bw_bih0 = (const float*)d_in[12];
    const float* bw_bhh0 = (const float*)d_in[13];
    const float* bw_Wih  = (const float*)d_in[14];
    const float* bw_Whh  = (const float*)d_in[15];
    const float* bw_bih  = (const float*)d_in[16];
    const float* bw_bhh  = (const float*)d_in[17];
    const float* W_mu    = (const float*)d_in[18];
    const float* b_mu    = (const float*)d_in[19];
    const float* W_lv    = (const float*)d_in[20];
    const float* b_lv    = (const float*)d_in[21];
    float* out = (float*)d_out;

    cudaFuncSetAttribute(gi_mma,  cudaFuncAttributeMaxDynamicSharedMemorySize, SMEM_GI);
    cudaFuncSetAttribute(gru_mma, cudaFuncAttributeMaxDynamicSharedMemorySize, SMEM_GRU);

    prep_x<<<2048, 256>>>(x);
    prep_w<<<256, 256>>>(fw_Wih0, 0, 0, 0);
    prep_w<<<256, 256>>>(bw_Wih0, 1, 0, 0);
    for (int l = 0; l < 2; l++) {
        prep_w<<<512, 256>>>(fw_Wih + (size_t)l * G3 * HH, 0, 1, l);
        prep_w<<<512, 256>>>(bw_Wih + (size_t)l * G3 * HH, 1, 1, l);
    }
    prep_w<<<512, 256>>>(fw_Whh0, 0, 2, 0);
    prep_w<<<512, 256>>>(bw_Whh0, 1, 2, 0);
    for (int l = 1; l < 3; l++) {
        prep_w<<<512, 256>>>(fw_Whh + (size_t)(l - 1) * G3 * HH, 0, 2, l);
        prep_w<<<512, 256>>>(bw_Whh + (size_t)(l - 1) * G3 * HH, 1, 2, l);
    }
    prep_b<<<6, 256>>>(fw_bih0, 0, 0, 0);
    prep_b<<<6, 256>>>(bw_bih0, 1, 0, 0);
    prep_b<<<6, 256>>>(fw_bhh0, 0, 1, 0);
    prep_b<<<6, 256>>>(bw_bhh0, 1, 1, 0);
    for (int l = 1; l < 3; l++) {
        prep_b<<<6, 256>>>(fw_bih + (size_t)(l - 1) * G3, 0, 0, l);
        prep_b<<<6, 256>>>(bw_bih + (size_t)(l - 1) * G3, 1, 0, l);
        prep_b<<<6, 256>>>(fw_bhh + (size_t)(l - 1) * G3, 0, 1, l);
        prep_b<<<6, 256>>>(bw_bhh + (size_t)(l - 1) * G3, 1, 1, l);
    }

    const dim3 ggi(8, (TT * BB) / 128, 2);
    const dim3 gst(8, 8, 2);
    for (int l = 0; l < 3; l++) {
        gi_mma<<<ggi, 256, SMEM_GI>>>(l);
        for (int t = 0; t < TT; t++)
            gru_mma<<<gst, 256, SMEM_GRU>>>(t, l);
    }
    proj_kernel<<<dim3(HH / 64, BB / 64, 2), 256>>>(W_mu, b_mu, W_lv, b_lv, out);
}

// round 6
// speedup vs baseline: 5.9351x; 1.2518x over previous
#include <cuda_runtime.h>
#include <cuda_fp16.h>
#include <cstdint>
#include <math.h>

#define TT 128
#define BB 512
#define DD 300
#define DPAD 320
#define HH 512
#define G3 1536

// gi kernel smem (CTA tile 128x192): A 16KB, Bhi 24KB, Blo 24KB
#define SO_A   0
#define SO_BHI 16384
#define SO_BLO 40960
#define STAGE  65536
#define SMEM_GI (2 * STAGE)

// gru kernel smem (CTA tile 64x192): A 8KB, Bhi 24KB, Blo 24KB
#define GSO_A   0
#define GSO_BHI 8192
#define GSO_BLO 32768
#define GSTAGE  57344
#define SMEM_GRU (2 * GSTAGE)

__device__ __forceinline__ uint32_t smem_u32(const void* p) {
    uint32_t a;
    asm("{ .reg .u64 t; cvta.to.shared.u64 t, %1; cvt.u32.u64 %0, t; }" : "=r"(a) : "l"(p));
    return a;
}
__device__ __forceinline__ void cp16(uint32_t s, const void* g) {
    asm volatile("cp.async.cg.shared.global [%0], [%1], 16;" :: "r"(s), "l"(g));
}
__device__ __forceinline__ void ldm4(uint32_t* r, uint32_t a) {
    asm volatile("ldmatrix.sync.aligned.m8n8.x4.shared.b16 {%0,%1,%2,%3}, [%4];"
                 : "=r"(r[0]), "=r"(r[1]), "=r"(r[2]), "=r"(r[3]) : "r"(a));
}
__device__ __forceinline__ void mma16816(float* c, const uint32_t* a, const uint32_t* b) {
    asm volatile("mma.sync.aligned.m16n8k16.row.col.f32.f16.f16.f32 "
        "{%0,%1,%2,%3}, {%4,%5,%6,%7}, {%8,%9}, {%0,%1,%2,%3};"
        : "+f"(c[0]), "+f"(c[1]), "+f"(c[2]), "+f"(c[3])
        : "r"(a[0]), "r"(a[1]), "r"(a[2]), "r"(a[3]), "r"(b[0]), "r"(b[1]));
}
__device__ __forceinline__ uint32_t swz(uint32_t o) { return o ^ ((o >> 3) & 0x70); }
__device__ __forceinline__ float sigmoidf_(float x) { return 1.f / (1.f + expf(-x)); }

__device__ __align__(16) __half g_x[(size_t)TT * BB * DPAD];
__device__ __align__(16) __half g_Wih0[2][2][(size_t)G3 * DPAD];
__device__ __align__(16) __half g_Wih[2][2][2][(size_t)G3 * HH];
__device__ __align__(16) __half g_Whh[2][3][2][(size_t)G3 * HH];
__device__ float g_bih[2][3][G3];
__device__ float g_bhh[2][3][G3];
__device__ __align__(16) __half g_h[2][(size_t)TT * BB * HH];
__device__ __align__(16) float g_gi[2][(size_t)TT * BB * G3];

// ---------------- prep: fp32 -> fp16 (weights: hi/lo split), gate-permute ----
__global__ void prep_x(const float* __restrict__ src) {
    const size_t total = (size_t)TT * BB * DPAD;
    for (size_t i = (size_t)blockIdx.x * blockDim.x + threadIdx.x; i < total;
         i += (size_t)gridDim.x * blockDim.x) {
        int r = (int)(i / DPAD), k = (int)(i % DPAD);
        g_x[i] = __float2half_rn((k < DD) ? src[(size_t)r * DD + k] : 0.f);
    }
}
__global__ void prep_w(const float* __restrict__ src, int dir, int kind, int l) {
    int K, Kpad; __half *hi, *lo;
    if (kind == 0)      { K = DD; Kpad = DPAD; hi = g_Wih0[dir][0]; lo = g_Wih0[dir][1]; }
    else if (kind == 1) { K = HH; Kpad = HH;   hi = g_Wih[dir][l][0]; lo = g_Wih[dir][l][1]; }
    else                { K = HH; Kpad = HH;   hi = g_Whh[dir][l][0]; lo = g_Whh[dir][l][1]; }
    const size_t total = (size_t)G3 * Kpad;
    for (size_t i = (size_t)blockIdx.x * blockDim.x + threadIdx.x; i < total;
         i += (size_t)gridDim.x * blockDim.x) {
        int r = (int)(i / Kpad), k = (int)(i % Kpad);
        int rem = r % 192;
        int sr = (rem >> 6) * HH + (r / 192) * 64 + (rem & 63);
        float v = (k < K) ? src[(size_t)sr * K + k] : 0.f;
        __half h = __float2half_rn(v);
        hi[i] = h; lo[i] = __float2half_rn(v - __half2float(h));
    }
}
__global__ void prep_b(const float* __restrict__ src, int dir, int which, int l) {
    int r = blockIdx.x * blockDim.x + threadIdx.x;
    if (r < G3) {
        int rem = r % 192;
        float v = src[(rem >> 6) * HH + (r / 192) * 64 + (rem & 63)];
        if (which == 0) g_bih[dir][l][r] = v; else g_bhh[dir][l][r] = v;
    }
}

// ================= gi GEMM path (CTA 128x192) =================
__device__ __forceinline__ void load_tile(
    uint32_t sbuf, const char* A, size_t lda,
    const char* Wh, const char* Wl, size_t ldw, int kt, int tid)
{
    const size_t kb = (size_t)kt * 128;
    for (int i = tid; i < 1024; i += 256) {
        int r = i >> 3, ch = (i & 7) * 16;
        uint32_t so = swz((uint32_t)(r * 128 + ch));
        cp16(sbuf + SO_A + so, A + (size_t)r * lda + kb + ch);
    }
    for (int i = tid; i < 1536; i += 256) {
        int r = i >> 3, ch = (i & 7) * 16;
        uint32_t so = swz((uint32_t)(r * 128 + ch));
        const size_t go = (size_t)r * ldw + kb + ch;
        cp16(sbuf + SO_BHI + so, Wh + go);
        cp16(sbuf + SO_BLO + so, Wl + go);
    }
    asm volatile("cp.async.commit_group;" ::: "memory");
}

__device__ __forceinline__ void compute_tile(
    uint32_t sbuf, int wm, int wn, int lane, float (&acc)[2][3][4][4])
{
    const int arow = wm * 32 + (lane & 15);
    const int acolsel = (lane >> 4) * 16;
    const int mat = lane >> 3;
    const int brow_in = (mat >> 1) * 8 + (lane & 7);
    const int bcol = (mat & 1) * 16;
    #pragma unroll
    for (int kk = 0; kk < 4; kk++) {
        uint32_t ah[2][4];
        #pragma unroll
        for (int mt = 0; mt < 2; mt++) {
            uint32_t o = swz((uint32_t)((arow + mt * 16) * 128 + kk * 32 + acolsel));
            ldm4(ah[mt], sbuf + SO_A + o);
        }
        #pragma unroll
        for (int g = 0; g < 3; g++) {
            #pragma unroll
            for (int p = 0; p < 2; p++) {
                uint32_t o = swz((uint32_t)((g * 64 + wn * 32 + p * 16 + brow_in) * 128
                                            + kk * 32 + bcol));
                uint32_t bh[4], bl[4];
                ldm4(bh, sbuf + SO_BHI + o);
                ldm4(bl, sbuf + SO_BLO + o);
                #pragma unroll
                for (int mt = 0; mt < 2; mt++) {
                    #pragma unroll
                    for (int q = 0; q < 2; q++) {
                        float* c = acc[mt][g][p * 2 + q];
                        mma16816(c, ah[mt], &bh[q * 2]);
                        mma16816(c, ah[mt], &bl[q * 2]);
                    }
                }
            }
        }
    }
}

__global__ __launch_bounds__(256) void gi_mma(int l)
{
    extern __shared__ char smem[];
    const uint32_t sb = smem_u32(smem);
    const int tid = threadIdx.x, lane = tid & 31, wid = tid >> 5;
    const int wm = wid & 3, wn = wid >> 2;
    const int dir = blockIdx.z, nblk = blockIdx.x, m0 = blockIdx.y * 128;

    const __half *A, *Wh, *Wl;
    int ld, NK; size_t arow0;
    if (l == 0) {
        ld = DPAD; NK = 5;
        int t = m0 / BB, tt = dir ? (TT - 1 - t) : t;
        arow0 = (size_t)tt * BB + (m0 % BB);
        A = g_x; Wh = g_Wih0[dir][0]; Wl = g_Wih0[dir][1];
    } else {
        ld = HH; NK = 8; arow0 = m0;
        A = g_h[dir];
        Wh = g_Wih[dir][l - 1][0]; Wl = g_Wih[dir][l - 1][1];
    }
    const size_t ldb = (size_t)ld * 2;
    const char* Ab  = (const char*)(A + arow0 * ld);
    const char* Whb = (const char*)(Wh + (size_t)nblk * 192 * ld);
    const char* Wlb = (const char*)(Wl + (size_t)nblk * 192 * ld);

    float acc[2][3][4][4];
    #pragma unroll
    for (int a = 0; a < 2; a++)
        #pragma unroll
        for (int b = 0; b < 3; b++)
            #pragma unroll
            for (int c = 0; c < 4; c++)
                #pragma unroll
                for (int d = 0; d < 4; d++) acc[a][b][c][d] = 0.f;

    load_tile(sb, Ab, ldb, Whb, Wlb, ldb, 0, tid);
    for (int kt = 0; kt < NK; kt++) {
        if (kt + 1 < NK) {
            load_tile(sb + ((kt + 1) & 1) * STAGE, Ab, ldb, Whb, Wlb, ldb, kt + 1, tid);
            asm volatile("cp.async.wait_group 1;" ::: "memory");
        } else {
            asm volatile("cp.async.wait_group 0;" ::: "memory");
        }
        __syncthreads();
        compute_tile(sb + (kt & 1) * STAGE, wm, wn, lane, acc);
        __syncthreads();
    }

    float* gout = g_gi[dir];
    const float* bias = g_bih[dir][l];
    #pragma unroll
    for (int mt = 0; mt < 2; mt++) {
        const int r0 = m0 + wm * 32 + mt * 16 + (lane >> 2);
        #pragma unroll
        for (int g = 0; g < 3; g++)
            #pragma unroll
            for (int nt = 0; nt < 4; nt++) {
                const int col = nblk * 192 + g * 64 + wn * 32 + nt * 8 + (lane & 3) * 2;
                const float b0 = bias[col], b1 = bias[col + 1];
                const float* c = acc[mt][g][nt];
                *(float2*)(gout + (size_t)r0 * G3 + col) = make_float2(c[0] + b0, c[1] + b1);
                *(float2*)(gout + (size_t)(r0 + 8) * G3 + col) = make_float2(c[2] + b0, c[3] + b1);
            }
    }
}

// ================= fused recurrent step (CTA 64x192, grid (8,8,2)) =================
__device__ __forceinline__ void load_tile_gru(
    uint32_t sbuf, const char* A, const char* Wh, const char* Wl, int kt, int tid)
{
    const size_t kb = (size_t)kt * 128;
    const size_t ldb = HH * 2;
    for (int i = tid; i < 512; i += 256) {
        int r = i >> 3, ch = (i & 7) * 16;
        uint32_t so = swz((uint32_t)(r * 128 + ch));
        cp16(sbuf + GSO_A + so, A + (size_t)r * ldb + kb + ch);
    }
    for (int i = tid; i < 1536; i += 256) {
        int r = i >> 3, ch = (i & 7) * 16;
        uint32_t so = swz((uint32_t)(r * 128 + ch));
        const size_t go = (size_t)r * ldb + kb + ch;
        cp16(sbuf + GSO_BHI + so, Wh + go);
        cp16(sbuf + GSO_BLO + so, Wl + go);
    }
    asm volatile("cp.async.commit_group;" ::: "memory");
}

__device__ __forceinline__ void compute_tile_gru(
    uint32_t sbuf, int wm, int wn, int lane, float (&acc)[2][3][2][4])
{
    const int arow = wm * 32 + (lane & 15);
    const int acolsel = (lane >> 4) * 16;
    const int mat = lane >> 3;
    const int brow_in = (mat >> 1) * 8 + (lane & 7);
    const int bcol = (mat & 1) * 16;
    #pragma unroll
    for (int kk = 0; kk < 4; kk++) {
        uint32_t ah[2][4];
        #pragma unroll
        for (int mt = 0; mt < 2; mt++) {
            uint32_t o = swz((uint32_t)((arow + mt * 16) * 128 + kk * 32 + acolsel));
            ldm4(ah[mt], sbuf + GSO_A + o);
        }
        #pragma unroll
        for (int g = 0; g < 3; g++) {
            uint32_t o = swz((uint32_t)((g * 64 + wn * 16 + brow_in) * 128 + kk * 32 + bcol));
            uint32_t bh[4], bl[4];
            ldm4(bh, sbuf + GSO_BHI + o);
            ldm4(bl, sbuf + GSO_BLO + o);
            #pragma unroll
            for (int mt = 0; mt < 2; mt++) {
                #pragma unroll
                for (int q = 0; q < 2; q++) {
                    float* c = acc[mt][g][q];
                    mma16816(c, ah[mt], &bh[q * 2]);
                    mma16816(c, ah[mt], &bl[q * 2]);
                }
            }
        }
    }
}

__global__ __launch_bounds__(256) void gru_mma(int t, int l)
{
    extern __shared__ char smem[];
    const uint32_t sb = smem_u32(smem);
    const int tid = threadIdx.x, lane = tid & 31, wid = tid >> 5;
    const int wm = wid & 1, wn = wid >> 1;
    const int dir = blockIdx.z, nblk = blockIdx.x, m0 = blockIdx.y * 64;

    float acc[2][3][2][4];
    #pragma unroll
    for (int a = 0; a < 2; a++)
        #pragma unroll
        for (int b = 0; b < 3; b++)
            #pragma unroll
            for (int c = 0; c < 2; c++)
                #pragma unroll
                for (int d = 0; d < 4; d++) acc[a][b][c][d] = 0.f;

    if (t > 0) {
        const size_t arow0 = (size_t)(t - 1) * BB + m0;
        const char* Ab  = (const char*)(g_h[dir] + arow0 * HH);
        const char* Whb = (const char*)(g_Whh[dir][l][0] + (size_t)nblk * 192 * HH);
        const char* Wlb = (const char*)(g_Whh[dir][l][1] + (size_t)nblk * 192 * HH);
        load_tile_gru(sb, Ab, Whb, Wlb, 0, tid);
        for (int kt = 0; kt < 8; kt++) {
            if (kt + 1 < 8) {
                load_tile_gru(sb + ((kt + 1) & 1) * GSTAGE, Ab, Whb, Wlb, kt + 1, tid);
                asm volatile("cp.async.wait_group 1;" ::: "memory");
            } else {
                asm volatile("cp.async.wait_group 0;" ::: "memory");
            }
            __syncthreads();
            compute_tile_gru(sb + (kt & 1) * GSTAGE, wm, wn, lane, acc);
            __syncthreads();
        }
    }

    const float* giP = g_gi[dir] + (size_t)t * BB * G3;
    const float* bh = g_bhh[dir][l];
    const __half* Ph = g_h[dir] + (size_t)(t - 1) * BB * HH;
    __half* Oh = g_h[dir] + (size_t)t * BB * HH;

    #pragma unroll
    for (int mt = 0; mt < 2; mt++)
        #pragma unroll
        for (int q = 0; q < 2; q++) {
            const int hl = wn * 16 + q * 8 + (lane & 3) * 2;
            const int cr = nblk * 192 + hl;
            const int hc = nblk * 64 + hl;
            const float* c_r = acc[mt][0][q];
            const float* c_z = acc[mt][1][q];
            const float* c_n = acc[mt][2][q];
            const float bhr0 = bh[cr], bhr1 = bh[cr + 1];
            const float bhz0 = bh[cr + 64], bhz1 = bh[cr + 65];
            const float bhn0 = bh[cr + 128], bhn1 = bh[cr + 129];
            #pragma unroll
            for (int hf = 0; hf < 2; hf++) {
                const int m = m0 + wm * 32 + mt * 16 + (lane >> 2) + hf * 8;
                const float* gim = giP + (size_t)m * G3;
                const float2 gr = *(const float2*)(gim + cr);
                const float2 gz = *(const float2*)(gim + cr + 64);
                const float2 gn = *(const float2*)(gim + cr + 128);
                float hp0 = 0.f, hp1 = 0.f;
                if (t > 0) {
                    __half2 ph = *(const __half2*)(Ph + (size_t)m * HH + hc);
                    hp0 = __half2float(ph.x);
                    hp1 = __half2float(ph.y);
                }
                const float rg0 = sigmoidf_(gr.x + bhr0 + c_r[hf * 2 + 0]);
                const float rg1 = sigmoidf_(gr.y + bhr1 + c_r[hf * 2 + 1]);
                const float zg0 = sigmoidf_(gz.x + bhz0 + c_z[hf * 2 + 0]);
                const float zg1 = sigmoidf_(gz.y + bhz1 + c_z[hf * 2 + 1]);
                const float ng0 = tanhf(gn.x + rg0 * (c_n[hf * 2 + 0] + bhn0));
                const float ng1 = tanhf(gn.y + rg1 * (c_n[hf * 2 + 1] + bhn1));
                const float h0 = (1.f - zg0) * ng0 + zg0 * hp0;
                const float h1 = (1.f - zg1) * ng1 + zg1 * hp1;
                __half2 hh;
                hh.x = __float2half_rn(h0);
                hh.y = __float2half_rn(h1);
                *(__half2*)(Oh + (size_t)m * HH + hc) = hh;
            }
        }
}

// ---------------- projection ----------------
__global__ __launch_bounds__(256) void proj_kernel(
    const float* __restrict__ Wmu, const float* __restrict__ bmu,
    const float* __restrict__ Wlv, const float* __restrict__ blv,
    float* __restrict__ out)
{
    __shared__ float As[16][66];
    __shared__ float Bs[16][66];
    const int which = blockIdx.z;
    const float* W = which ? Wlv : Wmu;
    const float* bias = which ? blv : bmu;
    const int n0 = blockIdx.x * 64, m0 = blockIdx.y * 64;
    const __half* hf = g_h[0] + ((size_t)(TT - 1) * BB + m0) * HH;
    const __half* hb = g_h[1] + ((size_t)(TT - 1) * BB + m0) * HH;
    const int tid = threadIdx.x, tx = tid & 15, ty = tid >> 4;
    float acc[4][4];
    #pragma unroll
    for (int i = 0; i < 4; i++)
        #pragma unroll
        for (int j = 0; j < 4; j++) acc[i][j] = 0.f;

    for (int k0 = 0; k0 < 2 * HH; k0 += 16) {
        #pragma unroll
        for (int i = 0; i < 4; i++) {
            const int e = tid + i * 256;
            const int kk = e & 15, mm = e >> 4;
            const int k = k0 + kk;
            As[kk][mm] = (k < HH) ? __half2float(hf[(size_t)mm * HH + k])
                                  : __half2float(hb[(size_t)mm * HH + k - HH]);
            Bs[kk][mm] = W[(size_t)(n0 + mm) * (2 * HH) + k];
        }
        __syncthreads();
        #pragma unroll
        for (int kk = 0; kk < 16; kk++) {
            float a[4], b[4];
            #pragma unroll
            for (int i = 0; i < 4; i++) a[i] = As[kk][ty * 4 + i];
            #pragma unroll
            for (int j = 0; j < 4; j++) b[j] = Bs[kk][tx * 4 + j];
            #pragma unroll
            for (int i = 0; i < 4; i++)
                #pragma unroll
                for (int j = 0; j < 4; j++) acc[i][j] += a[i] * b[j];
        }
        __syncthreads();
    }
    #pragma unroll
    for (int i = 0; i < 4; i++) {
        const int m = m0 + ty * 4 + i;
        #pragma unroll
        for (int j = 0; j < 4; j++) {
            const int n = n0 + tx * 4 + j;
            out[(size_t)which * BB * HH + (size_t)m * HH + n] = acc[i][j] + bias[n];
        }
    }
}

extern "C" void kernel_launch(void* const* d_in, const int* in_sizes, int n_in,
                              void* d_out, int out_size)
{
    (void)in_sizes; (void)n_in; (void)out_size;
    const float* x       = (const float*)d_in[0];
    const float* fw_Wih0 = (const float*)d_in[2];
    const float* fw_Whh0 = (const float*)d_in[3];
    const float* fw_bih0 = (const float*)d_in[4];
    const float* fw_bhh0 = (const float*)d_in[5];
    const float* fw_Wih  = (const float*)d_in[6];
    const float* fw_Whh  = (const float*)d_in[7];
    const float* fw_bih  = (const float*)d_in[8];
    const float* fw_bhh  = (const float*)d_in[9];
    const float* bw_Wih0 = (const float*)d_in[10];
    const float* bw_Whh0 = (const float*)d_in[11];
    const float* bw_bih0 = (const float*)d_in[12];
    const float* bw_bhh0 = (const float*)d_in[13];
    const float* bw_Wih  = (const float*)d_in[14];
    const float* bw_Whh  = (const float*)d_in[15];
    const float* bw_bih  = (const float*)d_in[16];
    const float* bw_bhh  = (const float*)d_in[17];
    const float* W_mu    = (const float*)d_in[18];
    const float* b_mu    = (const float*)d_in[19];
    const float* W_lv    = (const float*)d_in[20];
    const float* b_lv    = (const float*)d_in[21];
    float* out = (float*)d_out;

    cudaFuncSetAttribute(gi_mma,  cudaFuncAttributeMaxDynamicSharedMemorySize, SMEM_GI);
    cudaFuncSetAttribute(gru_mma, cudaFuncAttributeMaxDynamicSharedMemorySize, SMEM_GRU);

    prep_x<<<2048, 256>>>(x);
    prep_w<<<256, 256>>>(fw_Wih0, 0, 0, 0);
    prep_w<<<256, 256>>>(bw_Wih0, 1, 0, 0);
    for (int l = 0; l < 2; l++) {
        prep_w<<<512, 256>>>(fw_Wih + (size_t)l * G3 * HH, 0, 1, l);
        prep_w<<<512, 256>>>(bw_Wih + (size_t)l * G3 * HH, 1, 1, l);
    }
    prep_w<<<512, 256>>>(fw_Whh0, 0, 2, 0);
    prep_w<<<512, 256>>>(bw_Whh0, 1, 2, 0);
    for (int l = 1; l < 3; l++) {
        prep_w<<<512, 256>>>(fw_Whh + (size_t)(l - 1) * G3 * HH, 0, 2, l);
        prep_w<<<512, 256>>>(bw_Whh + (size_t)(l - 1) * G3 * HH, 1, 2, l);
    }
    prep_b<<<6, 256>>>(fw_bih0, 0, 0, 0);
    prep_b<<<6, 256>>>(bw_bih0, 1, 0, 0);
    prep_b<<<6, 256>>>(fw_bhh0, 0, 1, 0);
    prep_b<<<6, 256>>>(bw_bhh0, 1, 1, 0);
    for (int l = 1; l < 3; l++) {
        prep_b<<<6, 256>>>(fw_bih + (size_t)(l - 1) * G3, 0, 0, l);
        prep_b<<<6, 256>>>(bw_bih + (size_t)(l - 1) * G3, 1, 0, l);
        prep_b<<<6, 256>>>(fw_bhh + (size_t)(l - 1) * G3, 0, 1, l);
        prep_b<<<6, 256>>>(bw_bhh + (size_t)(l - 1) * G3, 1, 1, l);
    }

    const dim3 ggi(8, (TT * BB) / 128, 2);
    const dim3 gst(8, 8, 2);
    for (int l = 0; l < 3; l++) {
        gi_mma<<<ggi, 256, SMEM_GI>>>(l);
        for (int t = 0; t < TT; t++)
            gru_mma<<<gst, 256, SMEM_GRU>>>(t, l);
    }
    proj_kernel<<<dim3(HH / 64, BB / 64, 2), 256>>>(W_mu, b_mu, W_lv, b_lv, out);
}

// round 7
// speedup vs baseline: 6.0209x; 1.0144x over previous
#include <cuda_runtime.h>
#include <cuda_fp16.h>
#include <cstdint>
#include <math.h>

#define TT 128
#define BB 512
#define DD 300
#define DPAD 320
#define HH 512
#define G3 1536

// gi kernel smem (CTA tile 128x192): A 16KB, Bhi 24KB, Blo 24KB; 3 stages
#define SO_A   0
#define SO_BHI 16384
#define SO_BLO 40960
#define STAGE  65536
#define SMEM_GI (3 * STAGE)

// gru kernel smem (CTA tile 64x192): A 8KB, Bhi 24KB, Blo 24KB; 3 stages
#define GSO_A   0
#define GSO_BHI 8192
#define GSO_BLO 32768
#define GSTAGE  57344
#define SMEM_GRU (3 * GSTAGE)

__device__ __forceinline__ uint32_t smem_u32(const void* p) {
    uint32_t a;
    asm("{ .reg .u64 t; cvta.to.shared.u64 t, %1; cvt.u32.u64 %0, t; }" : "=r"(a) : "l"(p));
    return a;
}
__device__ __forceinline__ void cp16(uint32_t s, const void* g) {
    asm volatile("cp.async.cg.shared.global [%0], [%1], 16;" :: "r"(s), "l"(g));
}
__device__ __forceinline__ void ldm4(uint32_t* r, uint32_t a) {
    asm volatile("ldmatrix.sync.aligned.m8n8.x4.shared.b16 {%0,%1,%2,%3}, [%4];"
                 : "=r"(r[0]), "=r"(r[1]), "=r"(r[2]), "=r"(r[3]) : "r"(a));
}
__device__ __forceinline__ void mma16816(float* c, const uint32_t* a, const uint32_t* b) {
    asm volatile("mma.sync.aligned.m16n8k16.row.col.f32.f16.f16.f32 "
        "{%0,%1,%2,%3}, {%4,%5,%6,%7}, {%8,%9}, {%0,%1,%2,%3};"
        : "+f"(c[0]), "+f"(c[1]), "+f"(c[2]), "+f"(c[3])
        : "r"(a[0]), "r"(a[1]), "r"(a[2]), "r"(a[3]), "r"(b[0]), "r"(b[1]));
}
__device__ __forceinline__ uint32_t swz(uint32_t o) { return o ^ ((o >> 3) & 0x70); }
__device__ __forceinline__ float sigmoidf_(float x) { return 1.f / (1.f + expf(-x)); }

__device__ __align__(16) __half g_x[(size_t)TT * BB * DPAD];
__device__ __align__(16) __half g_Wih0[2][2][(size_t)G3 * DPAD];
__device__ __align__(16) __half g_Wih[2][2][2][(size_t)G3 * HH];
__device__ __align__(16) __half g_Whh[2][3][2][(size_t)G3 * HH];
__device__ float g_bih[2][3][G3];
__device__ float g_bhh[2][3][G3];
__device__ __align__(16) __half g_h[2][(size_t)TT * BB * HH];
__device__ __align__(16) float g_gi[2][(size_t)TT * BB * G3];

// ---------------- prep ----------------
__global__ void prep_x(const float* __restrict__ src) {
    const size_t total = (size_t)TT * BB * DPAD;
    for (size_t i = (size_t)blockIdx.x * blockDim.x + threadIdx.x; i < total;
         i += (size_t)gridDim.x * blockDim.x) {
        int r = (int)(i / DPAD), k = (int)(i % DPAD);
        g_x[i] = __float2half_rn((k < DD) ? src[(size_t)r * DD + k] : 0.f);
    }
}
__global__ void prep_w(const float* __restrict__ src, int dir, int kind, int l) {
    int K, Kpad; __half *hi, *lo;
    if (kind == 0)      { K = DD; Kpad = DPAD; hi = g_Wih0[dir][0]; lo = g_Wih0[dir][1]; }
    else if (kind == 1) { K = HH; Kpad = HH;   hi = g_Wih[dir][l][0]; lo = g_Wih[dir][l][1]; }
    else                { K = HH; Kpad = HH;   hi = g_Whh[dir][l][0]; lo = g_Whh[dir][l][1]; }
    const size_t total = (size_t)G3 * Kpad;
    for (size_t i = (size_t)blockIdx.x * blockDim.x + threadIdx.x; i < total;
         i += (size_t)gridDim.x * blockDim.x) {
        int r = (int)(i / Kpad), k = (int)(i % Kpad);
        int rem = r % 192;
        int sr = (rem >> 6) * HH + (r / 192) * 64 + (rem & 63);
        float v = (k < K) ? src[(size_t)sr * K + k] : 0.f;
        __half h = __float2half_rn(v);
        hi[i] = h; lo[i] = __float2half_rn(v - __half2float(h));
    }
}
__global__ void prep_b(const float* __restrict__ src, int dir, int which, int l) {
    int r = blockIdx.x * blockDim.x + threadIdx.x;
    if (r < G3) {
        int rem = r % 192;
        float v = src[(rem >> 6) * HH + (r / 192) * 64 + (rem & 63)];
        if (which == 0) g_bih[dir][l][r] = v; else g_bhh[dir][l][r] = v;
    }
}

// ================= gi GEMM path (CTA 128x192, 3-stage) =================
__device__ __forceinline__ void load_tile(
    uint32_t sbuf, const char* A, size_t lda,
    const char* Wh, const char* Wl, size_t ldw, int kt, int tid)
{
    const size_t kb = (size_t)kt * 128;
    for (int i = tid; i < 1024; i += 256) {
        int r = i >> 3, ch = (i & 7) * 16;
        uint32_t so = swz((uint32_t)(r * 128 + ch));
        cp16(sbuf + SO_A + so, A + (size_t)r * lda + kb + ch);
    }
    for (int i = tid; i < 1536; i += 256) {
        int r = i >> 3, ch = (i & 7) * 16;
        uint32_t so = swz((uint32_t)(r * 128 + ch));
        const size_t go = (size_t)r * ldw + kb + ch;
        cp16(sbuf + SO_BHI + so, Wh + go);
        cp16(sbuf + SO_BLO + so, Wl + go);
    }
    asm volatile("cp.async.commit_group;" ::: "memory");
}

__device__ __forceinline__ void compute_tile(
    uint32_t sbuf, int wm, int wn, int lane, float (&acc)[2][3][4][4])
{
    const int arow = wm * 32 + (lane & 15);
    const int acolsel = (lane >> 4) * 16;
    const int mat = lane >> 3;
    const int brow_in = (mat >> 1) * 8 + (lane & 7);
    const int bcol = (mat & 1) * 16;
    #pragma unroll
    for (int kk = 0; kk < 4; kk++) {
        uint32_t ah[2][4];
        #pragma unroll
        for (int mt = 0; mt < 2; mt++) {
            uint32_t o = swz((uint32_t)((arow + mt * 16) * 128 + kk * 32 + acolsel));
            ldm4(ah[mt], sbuf + SO_A + o);
        }
        #pragma unroll
        for (int g = 0; g < 3; g++) {
            #pragma unroll
            for (int p = 0; p < 2; p++) {
                uint32_t o = swz((uint32_t)((g * 64 + wn * 32 + p * 16 + brow_in) * 128
                                            + kk * 32 + bcol));
                uint32_t bh[4], bl[4];
                ldm4(bh, sbuf + SO_BHI + o);
                ldm4(bl, sbuf + SO_BLO + o);
                #pragma unroll
                for (int mt = 0; mt < 2; mt++) {
                    #pragma unroll
                    for (int q = 0; q < 2; q++) {
                        float* c = acc[mt][g][p * 2 + q];
                        mma16816(c, ah[mt], &bh[q * 2]);
                        mma16816(c, ah[mt], &bl[q * 2]);
                    }
                }
            }
        }
    }
}

__global__ __launch_bounds__(256) void gi_mma(int l)
{
    extern __shared__ char smem[];
    const uint32_t sb = smem_u32(smem);
    const int tid = threadIdx.x, lane = tid & 31, wid = tid >> 5;
    const int wm = wid & 3, wn = wid >> 2;
    const int dir = blockIdx.z, nblk = blockIdx.x, m0 = blockIdx.y * 128;

    const __half *A, *Wh, *Wl;
    int ld, NK; size_t arow0;
    if (l == 0) {
        ld = DPAD; NK = 5;
        int t = m0 / BB, tt = dir ? (TT - 1 - t) : t;
        arow0 = (size_t)tt * BB + (m0 % BB);
        A = g_x; Wh = g_Wih0[dir][0]; Wl = g_Wih0[dir][1];
    } else {
        ld = HH; NK = 8; arow0 = m0;
        A = g_h[dir];
        Wh = g_Wih[dir][l - 1][0]; Wl = g_Wih[dir][l - 1][1];
    }
    const size_t ldb = (size_t)ld * 2;
    const char* Ab  = (const char*)(A + arow0 * ld);
    const char* Whb = (const char*)(Wh + (size_t)nblk * 192 * ld);
    const char* Wlb = (const char*)(Wl + (size_t)nblk * 192 * ld);

    float acc[2][3][4][4];
    #pragma unroll
    for (int a = 0; a < 2; a++)
        #pragma unroll
        for (int b = 0; b < 3; b++)
            #pragma unroll
            for (int c = 0; c < 4; c++)
                #pragma unroll
                for (int d = 0; d < 4; d++) acc[a][b][c][d] = 0.f;

    // 3-stage pipeline, one sync per chunk
    uint32_t sstage[3] = { sb, sb + STAGE, sb + 2 * STAGE };
    load_tile(sstage[0], Ab, ldb, Whb, Wlb, ldb, 0, tid);
    load_tile(sstage[1], Ab, ldb, Whb, Wlb, ldb, 1, tid);
    int slot = 0;
    for (int kt = 0; kt < NK; kt++) {
        if (kt + 1 < NK) asm volatile("cp.async.wait_group 1;" ::: "memory");
        else             asm volatile("cp.async.wait_group 0;" ::: "memory");
        __syncthreads();
        if (kt + 2 < NK) {
            int ns = slot + 2; if (ns >= 3) ns -= 3;
            load_tile(sstage[ns], Ab, ldb, Whb, Wlb, ldb, kt + 2, tid);
        }
        compute_tile(sstage[slot], wm, wn, lane, acc);
        if (++slot == 3) slot = 0;
    }

    float* gout = g_gi[dir];
    const float* bias = g_bih[dir][l];
    #pragma unroll
    for (int mt = 0; mt < 2; mt++) {
        const int r0 = m0 + wm * 32 + mt * 16 + (lane >> 2);
        #pragma unroll
        for (int g = 0; g < 3; g++)
            #pragma unroll
            for (int nt = 0; nt < 4; nt++) {
                const int col = nblk * 192 + g * 64 + wn * 32 + nt * 8 + (lane & 3) * 2;
                const float b0 = bias[col], b1 = bias[col + 1];
                const float* c = acc[mt][g][nt];
                *(float2*)(gout + (size_t)r0 * G3 + col) = make_float2(c[0] + b0, c[1] + b1);
                *(float2*)(gout + (size_t)(r0 + 8) * G3 + col) = make_float2(c[2] + b0, c[3] + b1);
            }
    }
}

// ================= fused recurrent step (CTA 64x192, 3-stage, grid (8,8,2)) =================
__device__ __forceinline__ void load_tile_gru(
    uint32_t sbuf, const char* A, const char* Wh, const char* Wl, int kt, int tid)
{
    const size_t kb = (size_t)kt * 128;
    const size_t ldb = HH * 2;
    for (int i = tid; i < 512; i += 256) {
        int r = i >> 3, ch = (i & 7) * 16;
        uint32_t so = swz((uint32_t)(r * 128 + ch));
        cp16(sbuf + GSO_A + so, A + (size_t)r * ldb + kb + ch);
    }
    for (int i = tid; i < 1536; i += 256) {
        int r = i >> 3, ch = (i & 7) * 16;
        uint32_t so = swz((uint32_t)(r * 128 + ch));
        const size_t go = (size_t)r * ldb + kb + ch;
        cp16(sbuf + GSO_BHI + so, Wh + go);
        cp16(sbuf + GSO_BLO + so, Wl + go);
    }
    asm volatile("cp.async.commit_group;" ::: "memory");
}

__device__ __forceinline__ void compute_tile_gru(
    uint32_t sbuf, int wm, int wn, int lane, float (&acc)[2][3][2][4])
{
    const int arow = wm * 32 + (lane & 15);
    const int acolsel = (lane >> 4) * 16;
    const int mat = lane >> 3;
    const int brow_in = (mat >> 1) * 8 + (lane & 7);
    const int bcol = (mat & 1) * 16;
    #pragma unroll
    for (int kk = 0; kk < 4; kk++) {
        uint32_t ah[2][4];
        #pragma unroll
        for (int mt = 0; mt < 2; mt++) {
            uint32_t o = swz((uint32_t)((arow + mt * 16) * 128 + kk * 32 + acolsel));
            ldm4(ah[mt], sbuf + GSO_A + o);
        }
        #pragma unroll
        for (int g = 0; g < 3; g++) {
            uint32_t o = swz((uint32_t)((g * 64 + wn * 16 + brow_in) * 128 + kk * 32 + bcol));
            uint32_t bh[4], bl[4];
            ldm4(bh, sbuf + GSO_BHI + o);
            ldm4(bl, sbuf + GSO_BLO + o);
            #pragma unroll
            for (int mt = 0; mt < 2; mt++) {
                #pragma unroll
                for (int q = 0; q < 2; q++) {
                    float* c = acc[mt][g][q];
                    mma16816(c, ah[mt], &bh[q * 2]);
                    mma16816(c, ah[mt], &bl[q * 2]);
                }
            }
        }
    }
}

__global__ __launch_bounds__(256) void gru_mma(int t, int l)
{
    extern __shared__ char smem[];
    const uint32_t sb = smem_u32(smem);
    const int tid = threadIdx.x, lane = tid & 31, wid = tid >> 5;
    const int wm = wid & 1, wn = wid >> 1;
    const int dir = blockIdx.z, nblk = blockIdx.x, m0 = blockIdx.y * 64;

    float acc[2][3][2][4];
    #pragma unroll
    for (int a = 0; a < 2; a++)
        #pragma unroll
        for (int b = 0; b < 3; b++)
            #pragma unroll
            for (int c = 0; c < 2; c++)
                #pragma unroll
                for (int d = 0; d < 4; d++) acc[a][b][c][d] = 0.f;

    if (t > 0) {
        const size_t arow0 = (size_t)(t - 1) * BB + m0;
        const char* Ab  = (const char*)(g_h[dir] + arow0 * HH);
        const char* Whb = (const char*)(g_Whh[dir][l][0] + (size_t)nblk * 192 * HH);
        const char* Wlb = (const char*)(g_Whh[dir][l][1] + (size_t)nblk * 192 * HH);
        uint32_t sstage[3] = { sb, sb + GSTAGE, sb + 2 * GSTAGE };
        load_tile_gru(sstage[0], Ab, Whb, Wlb, 0, tid);
        load_tile_gru(sstage[1], Ab, Whb, Wlb, 1, tid);
        int slot = 0;
        for (int kt = 0; kt < 8; kt++) {
            if (kt + 1 < 8) asm volatile("cp.async.wait_group 1;" ::: "memory");
            else            asm volatile("cp.async.wait_group 0;" ::: "memory");
            __syncthreads();
            if (kt + 2 < 8) {
                int ns = slot + 2; if (ns >= 3) ns -= 3;
                load_tile_gru(sstage[ns], Ab, Whb, Wlb, kt + 2, tid);
            }
            compute_tile_gru(sstage[slot], wm, wn, lane, acc);
            if (++slot == 3) slot = 0;
        }
    }

    const float* giP = g_gi[dir] + (size_t)t * BB * G3;
    const float* bh = g_bhh[dir][l];
    const __half* Ph = g_h[dir] + (size_t)(t - 1) * BB * HH;
    __half* Oh = g_h[dir] + (size_t)t * BB * HH;

    #pragma unroll
    for (int mt = 0; mt < 2; mt++)
        #pragma unroll
        for (int q = 0; q < 2; q++) {
            const int hl = wn * 16 + q * 8 + (lane & 3) * 2;
            const int cr = nblk * 192 + hl;
            const int hc = nblk * 64 + hl;
            const float* c_r = acc[mt][0][q];
            const float* c_z = acc[mt][1][q];
            const float* c_n = acc[mt][2][q];
            const float bhr0 = bh[cr], bhr1 = bh[cr + 1];
            const float bhz0 = bh[cr + 64], bhz1 = bh[cr + 65];
            const float bhn0 = bh[cr + 128], bhn1 = bh[cr + 129];
            #pragma unroll
            for (int hf = 0; hf < 2; hf++) {
                const int m = m0 + wm * 32 + mt * 16 + (lane >> 2) + hf * 8;
                const float* gim = giP + (size_t)m * G3;
                const float2 gr = *(const float2*)(gim + cr);
                const float2 gz = *(const float2*)(gim + cr + 64);
                const float2 gn = *(const float2*)(gim + cr + 128);
                float hp0 = 0.f, hp1 = 0.f;
                if (t > 0) {
                    __half2 ph = *(const __half2*)(Ph + (size_t)m * HH + hc);
                    hp0 = __half2float(ph.x);
                    hp1 = __half2float(ph.y);
                }
                const float rg0 = sigmoidf_(gr.x + bhr0 + c_r[hf * 2 + 0]);
                const float rg1 = sigmoidf_(gr.y + bhr1 + c_r[hf * 2 + 1]);
                const float zg0 = sigmoidf_(gz.x + bhz0 + c_z[hf * 2 + 0]);
                const float zg1 = sigmoidf_(gz.y + bhz1 + c_z[hf * 2 + 1]);
                const float ng0 = tanhf(gn.x + rg0 * (c_n[hf * 2 + 0] + bhn0));
                const float ng1 = tanhf(gn.y + rg1 * (c_n[hf * 2 + 1] + bhn1));
                const float h0 = (1.f - zg0) * ng0 + zg0 * hp0;
                const float h1 = (1.f - zg1) * ng1 + zg1 * hp1;
                __half2 hh;
                hh.x = __float2half_rn(h0);
                hh.y = __float2half_rn(h1);
                *(__half2*)(Oh + (size_t)m * HH + hc) = hh;
            }
        }
}

// ---------------- projection ----------------
__global__ __launch_bounds__(256) void proj_kernel(
    const float* __restrict__ Wmu, const float* __restrict__ bmu,
    const float* __restrict__ Wlv, const float* __restrict__ blv,
    float* __restrict__ out)
{
    __shared__ float As[16][66];
    __shared__ float Bs[16][66];
    const int which = blockIdx.z;
    const float* W = which ? Wlv : Wmu;
    const float* bias = which ? blv : bmu;
    const int n0 = blockIdx.x * 64, m0 = blockIdx.y * 64;
    const __half* hf = g_h[0] + ((size_t)(TT - 1) * BB + m0) * HH;
    const __half* hb = g_h[1] + ((size_t)(TT - 1) * BB + m0) * HH;
    const int tid = threadIdx.x, tx = tid & 15, ty = tid >> 4;
    float acc[4][4];
    #pragma unroll
    for (int i = 0; i < 4; i++)
        #pragma unroll
        for (int j = 0; j < 4; j++) acc[i][j] = 0.f;

    for (int k0 = 0; k0 < 2 * HH; k0 += 16) {
        #pragma unroll
        for (int i = 0; i < 4; i++) {
            const int e = tid + i * 256;
            const int kk = e & 15, mm = e >> 4;
            const int k = k0 + kk;
            As[kk][mm] = (k < HH) ? __half2float(hf[(size_t)mm * HH + k])
                                  : __half2float(hb[(size_t)mm * HH + k - HH]);
            Bs[kk][mm] = W[(size_t)(n0 + mm) * (2 * HH) + k];
        }
        __syncthreads();
        #pragma unroll
        for (int kk = 0; kk < 16; kk++) {
            float a[4], b[4];
            #pragma unroll
            for (int i = 0; i < 4; i++) a[i] = As[kk][ty * 4 + i];
            #pragma unroll
            for (int j = 0; j < 4; j++) b[j] = Bs[kk][tx * 4 + j];
            #pragma unroll
            for (int i = 0; i < 4; i++)
                #pragma unroll
                for (int j = 0; j < 4; j++) acc[i][j] += a[i] * b[j];
        }
        __syncthreads();
    }
    #pragma unroll
    for (int i = 0; i < 4; i++) {
        const int m = m0 + ty * 4 + i;
        #pragma unroll
        for (int j = 0; j < 4; j++) {
            const int n = n0 + tx * 4 + j;
            out[(size_t)which * BB * HH + (size_t)m * HH + n] = acc[i][j] + bias[n];
        }
    }
}

extern "C" void kernel_launch(void* const* d_in, const int* in_sizes, int n_in,
                              void* d_out, int out_size)
{
    (void)in_sizes; (void)n_in; (void)out_size;
    const float* x       = (const float*)d_in[0];
    const float* fw_Wih0 = (const float*)d_in[2];
    const float* fw_Whh0 = (const float*)d_in[3];
    const float* fw_bih0 = (const float*)d_in[4];
    const float* fw_bhh0 = (const float*)d_in[5];
    const float* fw_Wih  = (const float*)d_in[6];
    const float* fw_Whh  = (const float*)d_in[7];
    const float* fw_bih  = (const float*)d_in[8];
    const float* fw_bhh  = (const float*)d_in[9];
    const float* bw_Wih0 = (const float*)d_in[10];
    const float* bw_Whh0 = (const float*)d_in[11];
    const float* bw_bih0 = (const float*)d_in[12];
    const float* bw_bhh0 = (const float*)d_in[13];
    const float* bw_Wih  = (const float*)d_in[14];
    const float* bw_Whh  = (const float*)d_in[15];
    const float* bw_bih  = (const float*)d_in[16];
    const float* bw_bhh  = (const float*)d_in[17];
    const float* W_mu    = (const float*)d_in[18];
    const float* b_mu    = (const float*)d_in[19];
    const float* W_lv    = (const float*)d_in[20];
    const float* b_lv    = (const float*)d_in[21];
    float* out = (float*)d_out;

    cudaFuncSetAttribute(gi_mma,  cudaFuncAttributeMaxDynamicSharedMemorySize, SMEM_GI);
    cudaFuncSetAttribute(gru_mma, cudaFuncAttributeMaxDynamicSharedMemorySize, SMEM_GRU);

    prep_x<<<2048, 256>>>(x);
    prep_w<<<256, 256>>>(fw_Wih0, 0, 0, 0);
    prep_w<<<256, 256>>>(bw_Wih0, 1, 0, 0);
    for (int l = 0; l < 2; l++) {
        prep_w<<<512, 256>>>(fw_Wih + (size_t)l * G3 * HH, 0, 1, l);
        prep_w<<<512, 256>>>(bw_Wih + (size_t)l * G3 * HH, 1, 1, l);
    }
    prep_w<<<512, 256>>>(fw_Whh0, 0, 2, 0);
    prep_w<<<512, 256>>>(bw_Whh0, 1, 2, 0);
    for (int l = 1; l < 3; l++) {
        prep_w<<<512, 256>>>(fw_Whh + (size_t)(l - 1) * G3 * HH, 0, 2, l);
        prep_w<<<512, 256>>>(bw_Whh + (size_t)(l - 1) * G3 * HH, 1, 2, l);
    }
    prep_b<<<6, 256>>>(fw_bih0, 0, 0, 0);
    prep_b<<<6, 256>>>(bw_bih0, 1, 0, 0);
    prep_b<<<6, 256>>>(fw_bhh0, 0, 1, 0);
    prep_b<<<6, 256>>>(bw_bhh0, 1, 1, 0);
    for (int l = 1; l < 3; l++) {
        prep_b<<<6, 256>>>(fw_bih + (size_t)(l - 1) * G3, 0, 0, l);
        prep_b<<<6, 256>>>(bw_bih + (size_t)(l - 1) * G3, 1, 0, l);
        prep_b<<<6, 256>>>(fw_bhh + (size_t)(l - 1) * G3, 0, 1, l);
        prep_b<<<6, 256>>>(bw_bhh + (size_t)(l - 1) * G3, 1, 1, l);
    }

    const dim3 ggi(8, (TT * BB) / 128, 2);
    const dim3 gst(8, 8, 2);
    for (int l = 0; l < 3; l++) {
        gi_mma<<<ggi, 256, SMEM_GI>>>(l);
        for (int t = 0; t < TT; t++)
            gru_mma<<<gst, 256, SMEM_GRU>>>(t, l);
    }
    proj_kernel<<<dim3(HH / 64, BB / 64, 2), 256>>>(W_mu, b_mu, W_lv, b_lv, out);
}